// round 8
// baseline (speedup 1.0000x reference)
#include <cuda_runtime.h>
#include <cuda_bf16.h>
#include <math.h>
#include <stdint.h>

// ---------------------------------------------------------------------------
// Problem constants
// ---------------------------------------------------------------------------
#define T_SEQ   2048
#define HIDDEN  2048
#define N_HEADS 16
#define N_KV    4
#define HEAD_DIM 128
#define QKV_N   ((N_HEADS + 2 * N_KV) * HEAD_DIM)   // 3072
#define K_OFF   (N_HEADS * HEAD_DIM)                 // 2048
#define V_OFF   (K_OFF + N_KV * HEAD_DIM)            // 2560
#define O_DIM   (N_HEADS * HEAD_DIM)                 // 2048

__device__ float g_qkv[T_SEQ * QKV_N];      // 24 MB
__device__ float g_attn[T_SEQ * O_DIM];     // 16 MB (tf32-rounded by attn)
__device__ float g_hid_r[T_SEQ * HIDDEN];   // rounded hidden [T][K]
__device__ float g_wqkv_t[QKV_N * HIDDEN];  // w_qkv^T rounded [N][K]
__device__ float g_wo_t[HIDDEN * O_DIM];    // w_o^T rounded   [N][K]

// ---------------------------------------------------------------------------
// helpers
// ---------------------------------------------------------------------------
__device__ __forceinline__ uint32_t f2tf32(float x) {
    uint32_t r;
    asm("cvt.rna.tf32.f32 %0, %1;\n" : "=r"(r) : "f"(x));
    return r;
}
__device__ __forceinline__ float roundtf(float x) {
    return __uint_as_float(f2tf32(x));
}
__device__ __forceinline__ void mma_tf32(float* d, const uint32_t* a,
                                         const uint32_t* b, const float* c) {
    asm volatile(
        "mma.sync.aligned.m16n8k8.row.col.f32.tf32.tf32.f32 "
        "{%0,%1,%2,%3}, {%4,%5,%6,%7}, {%8,%9}, {%10,%11,%12,%13};\n"
        : "=f"(d[0]), "=f"(d[1]), "=f"(d[2]), "=f"(d[3])
        : "r"(a[0]), "r"(a[1]), "r"(a[2]), "r"(a[3]),
          "r"(b[0]), "r"(b[1]),
          "f"(c[0]), "f"(c[1]), "f"(c[2]), "f"(c[3]));
}
__device__ __forceinline__ void mma_tf32_b(float* d, const uint32_t* a,
                                           uint32_t b0, uint32_t b1,
                                           const float* c) {
    asm volatile(
        "mma.sync.aligned.m16n8k8.row.col.f32.tf32.tf32.f32 "
        "{%0,%1,%2,%3}, {%4,%5,%6,%7}, {%8,%9}, {%10,%11,%12,%13};\n"
        : "=f"(d[0]), "=f"(d[1]), "=f"(d[2]), "=f"(d[3])
        : "r"(a[0]), "r"(a[1]), "r"(a[2]), "r"(a[3]),
          "r"(b0), "r"(b1),
          "f"(c[0]), "f"(c[1]), "f"(c[2]), "f"(c[3]));
}
__device__ __forceinline__ void ldsm_x4(uint32_t* r, uint32_t saddr) {
    asm volatile(
        "ldmatrix.sync.aligned.m8n8.x4.shared.b16 {%0,%1,%2,%3}, [%4];\n"
        : "=r"(r[0]), "=r"(r[1]), "=r"(r[2]), "=r"(r[3]) : "r"(saddr));
}
__device__ __forceinline__ void cp16(uint32_t saddr, const void* g) {
    asm volatile("cp.async.cg.shared.global [%0], [%1], 16;\n"
                 :: "r"(saddr), "l"(g));
}
__device__ __forceinline__ void cp_commit() {
    asm volatile("cp.async.commit_group;\n" ::: "memory");
}
__device__ __forceinline__ void cp_wait0() {
    asm volatile("cp.async.wait_group 0;\n" ::: "memory");
}
__device__ __forceinline__ uint32_t s2u(const void* p) {
    return (uint32_t)__cvta_generic_to_shared(p);
}

// ---------------------------------------------------------------------------
// prep: tf32 round-copy and transpose+round (weights -> [N][K])
// ---------------------------------------------------------------------------
__global__ __launch_bounds__(256) void round_tf32_kernel(
    const float4* __restrict__ src, float4* __restrict__ dst)
{
    const int i = blockIdx.x * 256 + threadIdx.x;
    float4 v = src[i];
    v.x = roundtf(v.x); v.y = roundtf(v.y);
    v.z = roundtf(v.z); v.w = roundtf(v.w);
    dst[i] = v;
}

// dst[n][k] = round_tf32(src[k][n]); K, N multiples of 32
__global__ __launch_bounds__(256) void transpose_round_kernel(
    const float* __restrict__ src, float* __restrict__ dst, int K, int N)
{
    __shared__ float t[32][33];
    const int tx = threadIdx.x & 31;
    const int ty = threadIdx.x >> 5;   // 0..7
    const int k0 = blockIdx.y * 32;
    const int n0 = blockIdx.x * 32;
#pragma unroll
    for (int i = 0; i < 4; i++)
        t[ty + 8 * i][tx] = roundtf(src[(size_t)(k0 + ty + 8 * i) * N + n0 + tx]);
    __syncthreads();
#pragma unroll
    for (int i = 0; i < 4; i++)
        dst[(size_t)(n0 + ty + 8 * i) * K + k0 + tx] = t[tx][ty + 8 * i];
}

// ---------------------------------------------------------------------------
// tf32 tensor-core GEMM with ldmatrix fragment loads.
// C[M,N] = A[M,K] @ Bt[N,K]^T, both K-major pre-rounded tf32.
// 128x128x32 tile, 256 threads, cp.async double-buffered.
// B frag pairing: x4 gives {n-lo/k-lo, n-hi/k-lo, n-lo/k-hi, n-hi/k-hi};
// correct frags are {m0,m2} (nf even) and {m1,m3} (nf odd).
// ---------------------------------------------------------------------------
#define GAS 36
#define GEMM_TILE_W (128 * GAS)
#define GEMM_SMEM_BYTES (4 * GEMM_TILE_W * 4)    // 2 stages x (A+B)

__global__ __launch_bounds__(256, 2) void gemm_tf32(
    const float* __restrict__ A, const float* __restrict__ Bt,
    float* __restrict__ C, int M, int N, int K)
{
    extern __shared__ uint32_t sh[];
    const int tid  = threadIdx.x;
    const int lane = tid & 31;
    const int wid  = tid >> 5;
    const int wm   = wid >> 1;      // 0..3
    const int wn   = wid & 1;       // 0..1
    const int brow = blockIdx.y * 128;
    const int bcol = blockIdx.x * 128;

    // ldmatrix per-lane row/col pieces
    const int lm   = lane >> 3;                   // matrix index 0..3
    const int lrow = (lm & 1) * 8 + (lane & 7);   // row within 16-row group
    const int lcol = (lm >> 1) * 4;               // word offset within k-tile

    // cp.async coordinates
    const int cr = tid >> 3;
    const int cc = (tid & 7) * 4;

    const uint32_t s_base = s2u(sh);

    float acc[2][8][4];
#pragma unroll
    for (int mf = 0; mf < 2; mf++)
#pragma unroll
        for (int nf = 0; nf < 8; nf++)
#pragma unroll
            for (int i = 0; i < 4; i++) acc[mf][nf][i] = 0.f;

    const int ntk = K >> 5;

#define GEMM_ISSUE(KT, BUF)                                                    \
    do {                                                                       \
        const int k0 = (KT) * 32;                                              \
        const uint32_t abuf = s_base + (BUF) * 2 * GEMM_TILE_W * 4;            \
        const uint32_t bbuf = abuf + GEMM_TILE_W * 4;                          \
        _Pragma("unroll")                                                      \
        for (int i = 0; i < 4; i++) {                                          \
            const int r = cr + 32 * i;                                         \
            cp16(abuf + (r * GAS + cc) * 4,                                    \
                 A + (size_t)(brow + r) * K + k0 + cc);                        \
            cp16(bbuf + (r * GAS + cc) * 4,                                    \
                 Bt + (size_t)(bcol + r) * K + k0 + cc);                       \
        }                                                                      \
        cp_commit();                                                           \
    } while (0)

    GEMM_ISSUE(0, 0);

    for (int kt = 0; kt < ntk; kt++) {
        cp_wait0();
        __syncthreads();
        if (kt + 1 < ntk) GEMM_ISSUE(kt + 1, (kt + 1) & 1);

        const uint32_t abuf = s_base + (kt & 1) * 2 * GEMM_TILE_W * 4;
        const uint32_t bbuf = abuf + GEMM_TILE_W * 4;
        const uint32_t a_lane = abuf + ((wm * 32 + lrow) * GAS + lcol) * 4;
        const uint32_t b_lane = bbuf + ((wn * 64 + lrow) * GAS + lcol) * 4;

#pragma unroll
        for (int ks = 0; ks < 4; ks++) {
            const int kk = ks * 8;
            uint32_t af[2][4], bm[4][4];
            ldsm_x4(af[0], a_lane + kk * 4);
            ldsm_x4(af[1], a_lane + (16 * GAS + kk) * 4);
#pragma unroll
            for (int np = 0; np < 4; np++)
                ldsm_x4(bm[np], b_lane + (np * 16 * GAS + kk) * 4);
#pragma unroll
            for (int mf = 0; mf < 2; mf++)
#pragma unroll
                for (int np = 0; np < 4; np++) {
                    mma_tf32_b(acc[mf][2 * np],     af[mf],
                               bm[np][0], bm[np][2], acc[mf][2 * np]);
                    mma_tf32_b(acc[mf][2 * np + 1], af[mf],
                               bm[np][1], bm[np][3], acc[mf][2 * np + 1]);
                }
        }
    }

    const int lr = lane >> 2;
    const int lc = lane & 3;
#pragma unroll
    for (int mf = 0; mf < 2; mf++)
#pragma unroll
        for (int nf = 0; nf < 8; nf++) {
            const int r = brow + wm * 32 + mf * 16 + lr;
            const int c = bcol + wn * 64 + nf * 8 + 2 * lc;
            *(float2*)(C + (size_t)r * N + c) =
                make_float2(acc[mf][nf][0], acc[mf][nf][1]);
            *(float2*)(C + (size_t)(r + 8) * N + c) =
                make_float2(acc[mf][nf][2], acc[mf][nf][3]);
        }
#undef GEMM_ISSUE
}

// ---------------------------------------------------------------------------
// mRoPE + tf32 pre-round (Q/K rotate+round, V round only)
// ---------------------------------------------------------------------------
__global__ void rope_kernel(const int* __restrict__ positions)
{
    const int t  = blockIdx.x;
    const int hy = blockIdx.y;          // 0..23
    const int j  = threadIdx.x;         // 0..63

    if (hy >= 20) {
        float* base = g_qkv + (size_t)t * QKV_N + V_OFF
                      + (hy - 20) * HEAD_DIM + 2 * j;
        base[0] = roundtf(base[0]);
        base[1] = roundtf(base[1]);
        return;
    }

    const int off = (hy < N_HEADS) ? hy * HEAD_DIM
                                   : K_OFF + (hy - N_HEADS) * HEAD_DIM;
    const int prow = (j >= 44) ? 0 : ((j & 1) ? 2 : 1);
    const float pos = (float)positions[prow * T_SEQ + t];
    const float inv = expf(-((float)j * (1.0f / 64.0f)) * 13.122363377404328f);
    const float ang = pos * inv;
    float sn, cs;
    sincosf(ang, &sn, &cs);

    float* base = g_qkv + (size_t)t * QKV_N + off + 2 * j;
    const float x1 = base[0];
    const float x2 = base[1];
    base[0] = roundtf(x1 * cs - x2 * sn);
    base[1] = roundtf(x2 * cs + x1 * sn);
}

// ---------------------------------------------------------------------------
// Causal flash attention: warp-owns-full-rows, ldmatrix K frags (fixed
// pairing), register shfl-transpose for P, cp.async double-buffered K/V.
// Block: 128 queries x 1 head, 256 threads, 8 warps x 16 rows.
// ---------------------------------------------------------------------------
#define AKS 132
#define AVS 136
#define ATTN_SMEM_WORDS (2 * 64 * AKS + 2 * 64 * AVS)
#define ATTN_SMEM_BYTES (ATTN_SMEM_WORDS * 4)

__global__ __launch_bounds__(256) void attn_tc_kernel()
{
    extern __shared__ uint32_t sm[];
    uint32_t* Kr = sm;                 // [2][64][132]  (rows = key, k-major)
    uint32_t* Vr = Kr + 2 * 64 * AKS;  // [2][64][136]

    const int tid  = threadIdx.x;
    const int lane = tid & 31;
    const int wid  = tid >> 5;         // 0..7 : query rows 16*wid
    const int lr   = lane >> 2;
    const int lc   = lane & 3;
    const int h    = blockIdx.y;
    const int qb   = gridDim.x - 1 - blockIdx.x;   // big tiles first
    const int kvh  = h >> 2;

    const int row0 = qb * 128 + wid * 16 + lr;

    const int lm   = lane >> 3;
    const int lrow = (lm & 1) * 8 + (lane & 7);
    const int lcol = (lm >> 1) * 4;

    const uint32_t kr_base = s2u(Kr);
    const uint32_t vr_base = s2u(Vr);
    const int ldr = tid >> 5;
    const int ldc = (tid & 31) * 4;

#define ATTN_ISSUE(J, BUF)                                                     \
    do {                                                                       \
        const uint32_t kb = kr_base + (BUF) * 64 * AKS * 4;                    \
        const uint32_t vb = vr_base + (BUF) * 64 * AVS * 4;                    \
        _Pragma("unroll")                                                      \
        for (int i = 0; i < 8; i++) {                                          \
            const int r = ldr + 8 * i;                                         \
            const size_t grow = (size_t)((J) * 64 + r) * QKV_N                 \
                                + kvh * HEAD_DIM + ldc;                        \
            cp16(kb + (r * AKS + ldc) * 4, g_qkv + grow + K_OFF);              \
            cp16(vb + (r * AVS + ldc) * 4, g_qkv + grow + V_OFF);              \
        }                                                                      \
        cp_commit();                                                           \
    } while (0)

    ATTN_ISSUE(0, 0);

    // ---- Q fragments straight from gmem (pre-rounded by rope) ----
    uint32_t qf[16][4];
    {
        const float* q0 = g_qkv + (size_t)row0 * QKV_N + h * HEAD_DIM;
        const float* q8 = q0 + 8 * (size_t)QKV_N;
#pragma unroll
        for (int ks = 0; ks < 16; ks++) {
            qf[ks][0] = __float_as_uint(q0[8 * ks + lc]);
            qf[ks][1] = __float_as_uint(q8[8 * ks + lc]);
            qf[ks][2] = __float_as_uint(q0[8 * ks + lc + 4]);
            qf[ks][3] = __float_as_uint(q8[8 * ks + lc + 4]);
        }
    }

    float m0 = -1e30f, m1 = -1e30f, l0 = 0.f, l1 = 0.f;
    float o[16][4];
#pragma unroll
    for (int nf = 0; nf < 16; nf++)
#pragma unroll
        for (int i = 0; i < 4; i++) o[nf][i] = 0.f;

    const float scale = 0.08838834764831844f;   // 128^-0.5
    const int jmax = 2 * qb + 1;
    const int wrow_lo = qb * 128 + wid * 16;

    for (int j = 0; j <= jmax; j++) {
        cp_wait0();
        __syncthreads();
        if (j < jmax) ATTN_ISSUE(j + 1, (j + 1) & 1);

        const bool active = (64 * j <= wrow_lo + 15);
        if (active) {
            const uint32_t kbuf = kr_base + (j & 1) * 64 * AKS * 4;
            const uint32_t k_lane = kbuf + (lrow * AKS + lcol) * 4;
            const uint32_t* Vb = Vr + (j & 1) * 64 * AVS;

            // ---- scores = Q @ K^T : warp tile 16 x 64 ----
            float sc[8][4];
#pragma unroll
            for (int nf = 0; nf < 8; nf++)
#pragma unroll
                for (int i = 0; i < 4; i++) sc[nf][i] = 0.f;

#pragma unroll
            for (int ks = 0; ks < 16; ks++) {
                const int kk = ks * 8;
                uint32_t bm[4][4];
#pragma unroll
                for (int np = 0; np < 4; np++)
                    ldsm_x4(bm[np], k_lane + (np * 16 * AKS + kk) * 4);
#pragma unroll
                for (int np = 0; np < 4; np++) {
                    mma_tf32_b(sc[2 * np],     qf[ks],
                               bm[np][0], bm[np][2], sc[2 * np]);
                    mma_tf32_b(sc[2 * np + 1], qf[ks],
                               bm[np][1], bm[np][3], sc[2 * np + 1]);
                }
            }

            // ---- scale + causal mask ----
            const bool needmask = (64 * j + 63 > wrow_lo);
#pragma unroll
            for (int nf = 0; nf < 8; nf++)
#pragma unroll
                for (int ci = 0; ci < 4; ci++) {
                    float s = sc[nf][ci] * scale;
                    if (needmask) {
                        const int col = 64 * j + nf * 8 + 2 * lc + (ci & 1);
                        const int row = row0 + ((ci >> 1) * 8);
                        if (col > row) s = -1e30f;
                    }
                    sc[nf][ci] = s;
                }

            // ---- warp-local row max ----
            float mx0 = sc[0][0], mx1 = sc[0][2];
#pragma unroll
            for (int nf = 0; nf < 8; nf++) {
                mx0 = fmaxf(mx0, fmaxf(sc[nf][0], sc[nf][1]));
                mx1 = fmaxf(mx1, fmaxf(sc[nf][2], sc[nf][3]));
            }
            mx0 = fmaxf(mx0, __shfl_xor_sync(0xffffffffu, mx0, 1));
            mx0 = fmaxf(mx0, __shfl_xor_sync(0xffffffffu, mx0, 2));
            mx1 = fmaxf(mx1, __shfl_xor_sync(0xffffffffu, mx1, 1));
            mx1 = fmaxf(mx1, __shfl_xor_sync(0xffffffffu, mx1, 2));

            const float mn0 = fmaxf(m0, mx0);
            const float mn1 = fmaxf(m1, mx1);
            const float a0 = __expf(m0 - mn0);
            const float a1 = __expf(m1 - mn1);
            m0 = mn0; m1 = mn1;

            // ---- p = exp(s - m); row sums ----
            float ls0 = 0.f, ls1 = 0.f;
#pragma unroll
            for (int nf = 0; nf < 8; nf++) {
                sc[nf][0] = __expf(sc[nf][0] - mn0);
                sc[nf][1] = __expf(sc[nf][1] - mn0);
                sc[nf][2] = __expf(sc[nf][2] - mn1);
                sc[nf][3] = __expf(sc[nf][3] - mn1);
                ls0 += sc[nf][0] + sc[nf][1];
                ls1 += sc[nf][2] + sc[nf][3];
            }
            ls0 += __shfl_xor_sync(0xffffffffu, ls0, 1);
            ls0 += __shfl_xor_sync(0xffffffffu, ls0, 2);
            ls1 += __shfl_xor_sync(0xffffffffu, ls1, 1);
            ls1 += __shfl_xor_sync(0xffffffffu, ls1, 2);
            l0 = l0 * a0 + ls0;
            l1 = l1 * a1 + ls1;

#pragma unroll
            for (int nf = 0; nf < 16; nf++) {
                o[nf][0] *= a0; o[nf][1] *= a0;
                o[nf][2] *= a1; o[nf][3] *= a1;
            }

            // ---- PV: shfl-transpose P (C-frag -> A-frag), then MMA ----
            const int src0 = lr * 4 + (lc >> 1);
            const int src1 = src0 + 2;
            const bool odd = (lc & 1);
#pragma unroll
            for (int ks = 0; ks < 8; ks++) {
                const float b0 = __shfl_sync(0xffffffffu, sc[ks][0], src0);
                const float b1 = __shfl_sync(0xffffffffu, sc[ks][1], src0);
                const float b2 = __shfl_sync(0xffffffffu, sc[ks][2], src0);
                const float b3 = __shfl_sync(0xffffffffu, sc[ks][3], src0);
                const float c0 = __shfl_sync(0xffffffffu, sc[ks][0], src1);
                const float c1 = __shfl_sync(0xffffffffu, sc[ks][1], src1);
                const float c2 = __shfl_sync(0xffffffffu, sc[ks][2], src1);
                const float c3 = __shfl_sync(0xffffffffu, sc[ks][3], src1);
                uint32_t pf[4];
                pf[0] = f2tf32(odd ? b1 : b0);
                pf[1] = f2tf32(odd ? b3 : b2);
                pf[2] = f2tf32(odd ? c1 : c0);
                pf[3] = f2tf32(odd ? c3 : c2);

                const int kk = ks * 8;
#pragma unroll
                for (int nf = 0; nf < 16; nf++) {
                    const int c = nf * 8 + lr;
                    uint32_t vf[2];
                    vf[0] = Vb[(kk + lc) * AVS + c];
                    vf[1] = Vb[(kk + lc + 4) * AVS + c];
                    mma_tf32(o[nf], pf, vf, o[nf]);
                }
            }
        }
    }
#undef ATTN_ISSUE

    // ---- epilogue: normalize, round to tf32, store ----
    const float i0 = 1.0f / l0;
    const float i1 = 1.0f / l1;
#pragma unroll
    for (int nf = 0; nf < 16; nf++) {
        const int c = h * HEAD_DIM + nf * 8 + 2 * lc;
        *(float2*)(g_attn + (size_t)row0 * O_DIM + c) =
            make_float2(roundtf(o[nf][0] * i0), roundtf(o[nf][1] * i0));
        *(float2*)(g_attn + (size_t)(row0 + 8) * O_DIM + c) =
            make_float2(roundtf(o[nf][2] * i1), roundtf(o[nf][3] * i1));
    }
}

// ---------------------------------------------------------------------------
// Launch
// ---------------------------------------------------------------------------
extern "C" void kernel_launch(void* const* d_in, const int* in_sizes, int n_in,
                              void* d_out, int out_size)
{
    const int*   positions = (const int*)d_in[0];
    const float* hidden    = (const float*)d_in[1];
    const float* w_qkv     = (const float*)d_in[2];
    const float* w_o       = (const float*)d_in[3];
    float*       out       = (float*)d_out;

    float *qkv_ptr, *attn_ptr, *hid_ptr, *wqkv_ptr, *wo_ptr;
    cudaGetSymbolAddress((void**)&qkv_ptr,  g_qkv);
    cudaGetSymbolAddress((void**)&attn_ptr, g_attn);
    cudaGetSymbolAddress((void**)&hid_ptr,  g_hid_r);
    cudaGetSymbolAddress((void**)&wqkv_ptr, g_wqkv_t);
    cudaGetSymbolAddress((void**)&wo_ptr,   g_wo_t);

    static int cfg = 0;
    if (!cfg) {
        cudaFuncSetAttribute(gemm_tf32,
                             cudaFuncAttributeMaxDynamicSharedMemorySize,
                             GEMM_SMEM_BYTES);
        cudaFuncSetAttribute(attn_tc_kernel,
                             cudaFuncAttributeMaxDynamicSharedMemorySize,
                             ATTN_SMEM_BYTES);
        cfg = 1;
    }

    // 0) prep: round hidden; transpose+round weights to [N][K]
    round_tf32_kernel<<<(T_SEQ * HIDDEN) / 1024, 256>>>(
        (const float4*)hidden, (float4*)hid_ptr);
    transpose_round_kernel<<<dim3(QKV_N / 32, HIDDEN / 32), 256>>>(
        w_qkv, wqkv_ptr, HIDDEN, QKV_N);
    transpose_round_kernel<<<dim3(HIDDEN / 32, O_DIM / 32), 256>>>(
        w_o, wo_ptr, O_DIM, HIDDEN);

    // 1) QKV projection: [2048,2048] @ [2048,3072]
    gemm_tf32<<<dim3(QKV_N / 128, T_SEQ / 128), 256, GEMM_SMEM_BYTES>>>(
        hid_ptr, wqkv_ptr, qkv_ptr, T_SEQ, QKV_N, HIDDEN);

    // 2) mRoPE + V rounding
    rope_kernel<<<dim3(T_SEQ, N_HEADS + 2 * N_KV), 64>>>(positions);

    // 3) Causal flash attention
    attn_tc_kernel<<<dim3(T_SEQ / 128, N_HEADS), 256, ATTN_SMEM_BYTES>>>();

    // 4) Output projection: [2048,2048] @ [2048,2048]
    gemm_tf32<<<dim3(O_DIM / 128, T_SEQ / 128), 256, GEMM_SMEM_BYTES>>>(
        attn_ptr, wo_ptr, out, T_SEQ, O_DIM, HIDDEN);
}

// round 9
// speedup vs baseline: 1.0265x; 1.0265x over previous
#include <cuda_runtime.h>
#include <cuda_bf16.h>
#include <math.h>
#include <stdint.h>

// ---------------------------------------------------------------------------
// Problem constants
// ---------------------------------------------------------------------------
#define T_SEQ   2048
#define HIDDEN  2048
#define N_HEADS 16
#define N_KV    4
#define HEAD_DIM 128
#define QKV_N   ((N_HEADS + 2 * N_KV) * HEAD_DIM)   // 3072
#define K_OFF   (N_HEADS * HEAD_DIM)                 // 2048
#define V_OFF   (K_OFF + N_KV * HEAD_DIM)            // 2560
#define O_DIM   (N_HEADS * HEAD_DIM)                 // 2048

__device__ float g_qkv[T_SEQ * QKV_N];      // 24 MB
__device__ float g_attn[T_SEQ * O_DIM];     // 16 MB (tf32-rounded by attn)
__device__ float g_hid_r[T_SEQ * HIDDEN];   // rounded hidden
__device__ float g_wqkv_r[HIDDEN * QKV_N];  // rounded w_qkv [K][N]
__device__ float g_wo_r[O_DIM * HIDDEN];    // rounded w_o   [K][N]

// ---------------------------------------------------------------------------
// helpers
// ---------------------------------------------------------------------------
__device__ __forceinline__ uint32_t f2tf32(float x) {
    uint32_t r;
    asm("cvt.rna.tf32.f32 %0, %1;\n" : "=r"(r) : "f"(x));
    return r;
}
__device__ __forceinline__ float roundtf(float x) {
    return __uint_as_float(f2tf32(x));
}
__device__ __forceinline__ void mma_tf32(float* d, const uint32_t* a,
                                         const uint32_t* b, const float* c) {
    asm volatile(
        "mma.sync.aligned.m16n8k8.row.col.f32.tf32.tf32.f32 "
        "{%0,%1,%2,%3}, {%4,%5,%6,%7}, {%8,%9}, {%10,%11,%12,%13};\n"
        : "=f"(d[0]), "=f"(d[1]), "=f"(d[2]), "=f"(d[3])
        : "r"(a[0]), "r"(a[1]), "r"(a[2]), "r"(a[3]),
          "r"(b[0]), "r"(b[1]),
          "f"(c[0]), "f"(c[1]), "f"(c[2]), "f"(c[3]));
}
__device__ __forceinline__ void cp16(uint32_t saddr, const void* g) {
    asm volatile("cp.async.cg.shared.global [%0], [%1], 16;\n"
                 :: "r"(saddr), "l"(g));
}
__device__ __forceinline__ void cp_commit() {
    asm volatile("cp.async.commit_group;\n" ::: "memory");
}
__device__ __forceinline__ void cp_wait0() {
    asm volatile("cp.async.wait_group 0;\n" ::: "memory");
}
__device__ __forceinline__ uint32_t s2u(const void* p) {
    return (uint32_t)__cvta_generic_to_shared(p);
}

// ---------------------------------------------------------------------------
// tf32 round-copy
// ---------------------------------------------------------------------------
__global__ __launch_bounds__(256) void round_tf32_kernel(
    const float4* __restrict__ src, float4* __restrict__ dst)
{
    const int i = blockIdx.x * 256 + threadIdx.x;
    float4 v = src[i];
    v.x = roundtf(v.x); v.y = roundtf(v.y);
    v.z = roundtf(v.z); v.w = roundtf(v.w);
    dst[i] = v;
}

// ---------------------------------------------------------------------------
// tf32 tensor-core GEMM, occupancy-optimized.
// C[M,N] = A[M,K] @ B[K,N], 64x128x32 CTA tile, 256 threads (8 warps,
// warp grid 2x4, warp tile 32x32), cp.async double-buffered, 3 CTAs/SM.
// ---------------------------------------------------------------------------
#define GAS 36
#define GBS 136
#define GEMM_BM 64
#define GEMM_STAGE_W (GEMM_BM * GAS + 32 * GBS)     // 6656 words
#define GEMM_SMEM_BYTES (2 * GEMM_STAGE_W * 4)      // 52 KB

__global__ __launch_bounds__(256, 3) void gemm_tf32(
    const float* __restrict__ A, const float* __restrict__ B,
    float* __restrict__ C, int M, int N, int K)
{
    extern __shared__ uint32_t sh[];
    const int tid  = threadIdx.x;
    const int lane = tid & 31;
    const int wid  = tid >> 5;
    const int wm   = wid >> 2;      // 0..1  -> rows 32*wm
    const int wn   = wid & 3;       // 0..3  -> cols 32*wn
    const int lr   = lane >> 2;
    const int lc   = lane & 3;
    const int brow = blockIdx.y * GEMM_BM;
    const int bcol = blockIdx.x * 128;

    // cp.async coords: A 64x32 (2 chunks), B 32x128 (4 chunks)
    const int ar = tid >> 3;              // 0..31 (+32)
    const int ac = (tid & 7) * 4;
    const int br = tid >> 5;              // 0..7  (+8)
    const int bc = (tid & 31) * 4;

    const uint32_t s_base = s2u(sh);

    float acc[2][4][4];
#pragma unroll
    for (int mf = 0; mf < 2; mf++)
#pragma unroll
        for (int nf = 0; nf < 4; nf++)
#pragma unroll
            for (int i = 0; i < 4; i++) acc[mf][nf][i] = 0.f;

    const int ntk = K >> 5;

#define GEMM_ISSUE(KT, BUF)                                                    \
    do {                                                                       \
        const int k0 = (KT) * 32;                                              \
        const uint32_t abuf = s_base + (BUF) * GEMM_STAGE_W * 4;               \
        const uint32_t bbuf = abuf + GEMM_BM * GAS * 4;                        \
        _Pragma("unroll")                                                      \
        for (int i = 0; i < 2; i++) {                                          \
            const int r = ar + 32 * i;                                         \
            cp16(abuf + (r * GAS + ac) * 4,                                    \
                 A + (size_t)(brow + r) * K + k0 + ac);                        \
        }                                                                      \
        _Pragma("unroll")                                                      \
        for (int i = 0; i < 4; i++) {                                          \
            const int r = br + 8 * i;                                          \
            cp16(bbuf + (r * GBS + bc) * 4,                                    \
                 B + (size_t)(k0 + r) * N + bcol + bc);                        \
        }                                                                      \
        cp_commit();                                                           \
    } while (0)

    GEMM_ISSUE(0, 0);

    for (int kt = 0; kt < ntk; kt++) {
        cp_wait0();
        __syncthreads();
        if (kt + 1 < ntk) GEMM_ISSUE(kt + 1, (kt + 1) & 1);

        const uint32_t* Ab = sh + (kt & 1) * GEMM_STAGE_W;
        const uint32_t* Bb = Ab + GEMM_BM * GAS;

#pragma unroll
        for (int ks = 0; ks < 4; ks++) {
            const int kk = ks * 8;
            uint32_t af[2][4], bf[4][2];
#pragma unroll
            for (int mf = 0; mf < 2; mf++) {
                const int r = wm * 32 + mf * 16 + lr;
                af[mf][0] = Ab[r * GAS + kk + lc];
                af[mf][1] = Ab[(r + 8) * GAS + kk + lc];
                af[mf][2] = Ab[r * GAS + kk + lc + 4];
                af[mf][3] = Ab[(r + 8) * GAS + kk + lc + 4];
            }
#pragma unroll
            for (int nf = 0; nf < 4; nf++) {
                const int c = wn * 32 + nf * 8 + lr;
                bf[nf][0] = Bb[(kk + lc) * GBS + c];
                bf[nf][1] = Bb[(kk + lc + 4) * GBS + c];
            }
#pragma unroll
            for (int mf = 0; mf < 2; mf++)
#pragma unroll
                for (int nf = 0; nf < 4; nf++)
                    mma_tf32(acc[mf][nf], af[mf], bf[nf], acc[mf][nf]);
        }
    }

#pragma unroll
    for (int mf = 0; mf < 2; mf++)
#pragma unroll
        for (int nf = 0; nf < 4; nf++) {
            const int r = brow + wm * 32 + mf * 16 + lr;
            const int c = bcol + wn * 32 + nf * 8 + 2 * lc;
            *(float2*)(C + (size_t)r * N + c) =
                make_float2(acc[mf][nf][0], acc[mf][nf][1]);
            *(float2*)(C + (size_t)(r + 8) * N + c) =
                make_float2(acc[mf][nf][2], acc[mf][nf][3]);
        }
#undef GEMM_ISSUE
}

// ---------------------------------------------------------------------------
// mRoPE + tf32 pre-round (Q/K rotate+round, V round only)
// ---------------------------------------------------------------------------
__global__ void rope_kernel(const int* __restrict__ positions)
{
    const int t  = blockIdx.x;
    const int hy = blockIdx.y;          // 0..23
    const int j  = threadIdx.x;         // 0..63

    if (hy >= 20) {
        float* base = g_qkv + (size_t)t * QKV_N + V_OFF
                      + (hy - 20) * HEAD_DIM + 2 * j;
        base[0] = roundtf(base[0]);
        base[1] = roundtf(base[1]);
        return;
    }

    const int off = (hy < N_HEADS) ? hy * HEAD_DIM
                                   : K_OFF + (hy - N_HEADS) * HEAD_DIM;
    const int prow = (j >= 44) ? 0 : ((j & 1) ? 2 : 1);
    const float pos = (float)positions[prow * T_SEQ + t];
    const float inv = expf(-((float)j * (1.0f / 64.0f)) * 13.122363377404328f);
    const float ang = pos * inv;
    float sn, cs;
    sincosf(ang, &sn, &cs);

    float* base = g_qkv + (size_t)t * QKV_N + off + 2 * j;
    const float x1 = base[0];
    const float x2 = base[1];
    base[0] = roundtf(x1 * cs - x2 * sn);
    base[1] = roundtf(x2 * cs + x1 * sn);
}

// ---------------------------------------------------------------------------
// Causal flash attention (R6 version, best known): warp-owns-full-rows,
// scalar K/V frag loads, register shfl-transpose for P, cp.async KV.
// Block: 128 queries x 1 head, 256 threads, 8 warps x 16 rows.
// ---------------------------------------------------------------------------
#define AKS 132
#define AVS 136
#define ATTN_SMEM_WORDS (2 * 64 * AKS + 2 * 64 * AVS)
#define ATTN_SMEM_BYTES (ATTN_SMEM_WORDS * 4)

__global__ __launch_bounds__(256) void attn_tc_kernel()
{
    extern __shared__ uint32_t sm[];
    uint32_t* Kr = sm;                 // [2][64][132]
    uint32_t* Vr = Kr + 2 * 64 * AKS;  // [2][64][136]

    const int tid  = threadIdx.x;
    const int lane = tid & 31;
    const int wid  = tid >> 5;         // 0..7 : query rows 16*wid
    const int lr   = lane >> 2;
    const int lc   = lane & 3;
    const int h    = blockIdx.y;
    const int qb   = gridDim.x - 1 - blockIdx.x;   // big tiles first
    const int kvh  = h >> 2;

    const int row0 = qb * 128 + wid * 16 + lr;

    const uint32_t kr_base = s2u(Kr);
    const uint32_t vr_base = s2u(Vr);
    const int ldr = tid >> 5;
    const int ldc = (tid & 31) * 4;

#define ATTN_ISSUE(J, BUF)                                                     \
    do {                                                                       \
        const uint32_t kb = kr_base + (BUF) * 64 * AKS * 4;                    \
        const uint32_t vb = vr_base + (BUF) * 64 * AVS * 4;                    \
        _Pragma("unroll")                                                      \
        for (int i = 0; i < 8; i++) {                                          \
            const int r = ldr + 8 * i;                                         \
            const size_t grow = (size_t)((J) * 64 + r) * QKV_N                 \
                                + kvh * HEAD_DIM + ldc;                        \
            cp16(kb + (r * AKS + ldc) * 4, g_qkv + grow + K_OFF);              \
            cp16(vb + (r * AVS + ldc) * 4, g_qkv + grow + V_OFF);              \
        }                                                                      \
        cp_commit();                                                           \
    } while (0)

    ATTN_ISSUE(0, 0);

    // ---- Q fragments straight from gmem (pre-rounded by rope) ----
    uint32_t qf[16][4];
    {
        const float* q0 = g_qkv + (size_t)row0 * QKV_N + h * HEAD_DIM;
        const float* q8 = q0 + 8 * (size_t)QKV_N;
#pragma unroll
        for (int ks = 0; ks < 16; ks++) {
            qf[ks][0] = __float_as_uint(q0[8 * ks + lc]);
            qf[ks][1] = __float_as_uint(q8[8 * ks + lc]);
            qf[ks][2] = __float_as_uint(q0[8 * ks + lc + 4]);
            qf[ks][3] = __float_as_uint(q8[8 * ks + lc + 4]);
        }
    }

    float m0 = -1e30f, m1 = -1e30f, l0 = 0.f, l1 = 0.f;
    float o[16][4];
#pragma unroll
    for (int nf = 0; nf < 16; nf++)
#pragma unroll
        for (int i = 0; i < 4; i++) o[nf][i] = 0.f;

    const float scale = 0.08838834764831844f;   // 128^-0.5
    const int jmax = 2 * qb + 1;
    const int wrow_lo = qb * 128 + wid * 16;

    for (int j = 0; j <= jmax; j++) {
        cp_wait0();
        __syncthreads();
        if (j < jmax) ATTN_ISSUE(j + 1, (j + 1) & 1);

        const bool active = (64 * j <= wrow_lo + 15);
        if (active) {
            const uint32_t* Kb = Kr + (j & 1) * 64 * AKS;
            const uint32_t* Vb = Vr + (j & 1) * 64 * AVS;

            // ---- scores = Q @ K^T : warp tile 16 x 64 ----
            float sc[8][4];
#pragma unroll
            for (int nf = 0; nf < 8; nf++)
#pragma unroll
                for (int i = 0; i < 4; i++) sc[nf][i] = 0.f;

#pragma unroll
            for (int ks = 0; ks < 16; ks++) {
                const int kk = ks * 8;
                uint32_t bf[8][2];
#pragma unroll
                for (int nf = 0; nf < 8; nf++) {
                    const int c = nf * 8 + lr;
                    bf[nf][0] = Kb[c * AKS + kk + lc];
                    bf[nf][1] = Kb[c * AKS + kk + lc + 4];
                }
#pragma unroll
                for (int nf = 0; nf < 8; nf++)
                    mma_tf32(sc[nf], qf[ks], bf[nf], sc[nf]);
            }

            // ---- scale + causal mask ----
            const bool needmask = (64 * j + 63 > wrow_lo);
#pragma unroll
            for (int nf = 0; nf < 8; nf++)
#pragma unroll
                for (int ci = 0; ci < 4; ci++) {
                    float s = sc[nf][ci] * scale;
                    if (needmask) {
                        const int col = 64 * j + nf * 8 + 2 * lc + (ci & 1);
                        const int row = row0 + ((ci >> 1) * 8);
                        if (col > row) s = -1e30f;
                    }
                    sc[nf][ci] = s;
                }

            // ---- warp-local row max ----
            float mx0 = sc[0][0], mx1 = sc[0][2];
#pragma unroll
            for (int nf = 0; nf < 8; nf++) {
                mx0 = fmaxf(mx0, fmaxf(sc[nf][0], sc[nf][1]));
                mx1 = fmaxf(mx1, fmaxf(sc[nf][2], sc[nf][3]));
            }
            mx0 = fmaxf(mx0, __shfl_xor_sync(0xffffffffu, mx0, 1));
            mx0 = fmaxf(mx0, __shfl_xor_sync(0xffffffffu, mx0, 2));
            mx1 = fmaxf(mx1, __shfl_xor_sync(0xffffffffu, mx1, 1));
            mx1 = fmaxf(mx1, __shfl_xor_sync(0xffffffffu, mx1, 2));

            const float mn0 = fmaxf(m0, mx0);
            const float mn1 = fmaxf(m1, mx1);
            const float a0 = __expf(m0 - mn0);
            const float a1 = __expf(m1 - mn1);
            m0 = mn0; m1 = mn1;

            // ---- p = exp(s - m); row sums ----
            float ls0 = 0.f, ls1 = 0.f;
#pragma unroll
            for (int nf = 0; nf < 8; nf++) {
                sc[nf][0] = __expf(sc[nf][0] - mn0);
                sc[nf][1] = __expf(sc[nf][1] - mn0);
                sc[nf][2] = __expf(sc[nf][2] - mn1);
                sc[nf][3] = __expf(sc[nf][3] - mn1);
                ls0 += sc[nf][0] + sc[nf][1];
                ls1 += sc[nf][2] + sc[nf][3];
            }
            ls0 += __shfl_xor_sync(0xffffffffu, ls0, 1);
            ls0 += __shfl_xor_sync(0xffffffffu, ls0, 2);
            ls1 += __shfl_xor_sync(0xffffffffu, ls1, 1);
            ls1 += __shfl_xor_sync(0xffffffffu, ls1, 2);
            l0 = l0 * a0 + ls0;
            l1 = l1 * a1 + ls1;

#pragma unroll
            for (int nf = 0; nf < 16; nf++) {
                o[nf][0] *= a0; o[nf][1] *= a0;
                o[nf][2] *= a1; o[nf][3] *= a1;
            }

            // ---- PV: shfl-transpose P (C-frag -> A-frag), then MMA ----
            const int src0 = lr * 4 + (lc >> 1);
            const int src1 = src0 + 2;
            const bool odd = (lc & 1);
#pragma unroll
            for (int ks = 0; ks < 8; ks++) {
                const float b0 = __shfl_sync(0xffffffffu, sc[ks][0], src0);
                const float b1 = __shfl_sync(0xffffffffu, sc[ks][1], src0);
                const float b2 = __shfl_sync(0xffffffffu, sc[ks][2], src0);
                const float b3 = __shfl_sync(0xffffffffu, sc[ks][3], src0);
                const float c0 = __shfl_sync(0xffffffffu, sc[ks][0], src1);
                const float c1 = __shfl_sync(0xffffffffu, sc[ks][1], src1);
                const float c2 = __shfl_sync(0xffffffffu, sc[ks][2], src1);
                const float c3 = __shfl_sync(0xffffffffu, sc[ks][3], src1);
                uint32_t pf[4];
                pf[0] = f2tf32(odd ? b1 : b0);
                pf[1] = f2tf32(odd ? b3 : b2);
                pf[2] = f2tf32(odd ? c1 : c0);
                pf[3] = f2tf32(odd ? c3 : c2);

                const int kk = ks * 8;
#pragma unroll
                for (int nf = 0; nf < 16; nf++) {
                    const int c = nf * 8 + lr;
                    uint32_t vf[2];
                    vf[0] = Vb[(kk + lc) * AVS + c];
                    vf[1] = Vb[(kk + lc + 4) * AVS + c];
                    mma_tf32(o[nf], pf, vf, o[nf]);
                }
            }
        }
    }
#undef ATTN_ISSUE

    // ---- epilogue: normalize, round to tf32, store ----
    const float i0 = 1.0f / l0;
    const float i1 = 1.0f / l1;
#pragma unroll
    for (int nf = 0; nf < 16; nf++) {
        const int c = h * HEAD_DIM + nf * 8 + 2 * lc;
        *(float2*)(g_attn + (size_t)row0 * O_DIM + c) =
            make_float2(roundtf(o[nf][0] * i0), roundtf(o[nf][1] * i0));
        *(float2*)(g_attn + (size_t)(row0 + 8) * O_DIM + c) =
            make_float2(roundtf(o[nf][2] * i1), roundtf(o[nf][3] * i1));
    }
}

// ---------------------------------------------------------------------------
// Launch
// ---------------------------------------------------------------------------
extern "C" void kernel_launch(void* const* d_in, const int* in_sizes, int n_in,
                              void* d_out, int out_size)
{
    const int*   positions = (const int*)d_in[0];
    const float* hidden    = (const float*)d_in[1];
    const float* w_qkv     = (const float*)d_in[2];
    const float* w_o       = (const float*)d_in[3];
    float*       out       = (float*)d_out;

    float *qkv_ptr, *attn_ptr, *hid_ptr, *wqkv_ptr, *wo_ptr;
    cudaGetSymbolAddress((void**)&qkv_ptr,  g_qkv);
    cudaGetSymbolAddress((void**)&attn_ptr, g_attn);
    cudaGetSymbolAddress((void**)&hid_ptr,  g_hid_r);
    cudaGetSymbolAddress((void**)&wqkv_ptr, g_wqkv_r);
    cudaGetSymbolAddress((void**)&wo_ptr,   g_wo_r);

    static int cfg = 0;
    if (!cfg) {
        cudaFuncSetAttribute(gemm_tf32,
                             cudaFuncAttributeMaxDynamicSharedMemorySize,
                             GEMM_SMEM_BYTES);
        cudaFuncSetAttribute(attn_tc_kernel,
                             cudaFuncAttributeMaxDynamicSharedMemorySize,
                             ATTN_SMEM_BYTES);
        cfg = 1;
    }

    // 0) tf32 pre-round of GEMM inputs
    round_tf32_kernel<<<(T_SEQ * HIDDEN) / 1024, 256>>>(
        (const float4*)hidden, (float4*)hid_ptr);
    round_tf32_kernel<<<(HIDDEN * QKV_N) / 1024, 256>>>(
        (const float4*)w_qkv, (float4*)wqkv_ptr);
    round_tf32_kernel<<<(O_DIM * HIDDEN) / 1024, 256>>>(
        (const float4*)w_o, (float4*)wo_ptr);

    // 1) QKV projection: [2048,2048] @ [2048,3072]
    gemm_tf32<<<dim3(QKV_N / 128, T_SEQ / GEMM_BM), 256, GEMM_SMEM_BYTES>>>(
        hid_ptr, wqkv_ptr, qkv_ptr, T_SEQ, QKV_N, HIDDEN);

    // 2) mRoPE + V rounding
    rope_kernel<<<dim3(T_SEQ, N_HEADS + 2 * N_KV), 64>>>(positions);

    // 3) Causal flash attention
    attn_tc_kernel<<<dim3(T_SEQ / 128, N_HEADS), 256, ATTN_SMEM_BYTES>>>();

    // 4) Output projection: [2048,2048] @ [2048,2048]
    gemm_tf32<<<dim3(O_DIM / 128, T_SEQ / GEMM_BM), 256, GEMM_SMEM_BYTES>>>(
        attn_ptr, wo_ptr, out, T_SEQ, O_DIM, HIDDEN);
}

// round 10
// speedup vs baseline: 1.2997x; 1.2661x over previous
#include <cuda_runtime.h>
#include <cuda_fp16.h>
#include <math.h>
#include <stdint.h>
#include <string.h>

// ---------------------------------------------------------------------------
// Problem constants
// ---------------------------------------------------------------------------
#define T_SEQ   2048
#define HIDDEN  2048
#define N_HEADS 16
#define N_KV    4
#define HEAD_DIM 128
#define QKV_N   ((N_HEADS + 2 * N_KV) * HEAD_DIM)   // 3072
#define K_OFF   (N_HEADS * HEAD_DIM)                 // 2048
#define V_OFF   (K_OFF + N_KV * HEAD_DIM)            // 2560
#define O_DIM   (N_HEADS * HEAD_DIM)                 // 2048

__device__ float    g_qkv[T_SEQ * QKV_N];               // fp32 QKV (24 MB)
__device__ uint32_t g_attn_h[T_SEQ * O_DIM / 2];        // fp16 attn out (8 MB)
__device__ uint32_t g_hid_h[T_SEQ * HIDDEN / 2];        // fp16 hidden (8 MB)
__device__ uint32_t g_wqkv_h[(HIDDEN / 2) * QKV_N];     // fp16 w_qkv k-pairs
__device__ uint32_t g_wo_h[(O_DIM / 2) * HIDDEN];       // fp16 w_o   k-pairs

// ---------------------------------------------------------------------------
// helpers
// ---------------------------------------------------------------------------
__device__ __forceinline__ uint32_t f2tf32(float x) {
    uint32_t r;
    asm("cvt.rna.tf32.f32 %0, %1;\n" : "=r"(r) : "f"(x));
    return r;
}
__device__ __forceinline__ float roundtf(float x) {
    return __uint_as_float(f2tf32(x));
}
__device__ __forceinline__ uint32_t packh2(float a, float b) {
    __half2 h = __floats2half2_rn(a, b);
    uint32_t u; memcpy(&u, &h, 4); return u;
}
// tf32 m16n8k8 (attention path)
__device__ __forceinline__ void mma_tf32(float* d, const uint32_t* a,
                                         const uint32_t* b, const float* c) {
    asm volatile(
        "mma.sync.aligned.m16n8k8.row.col.f32.tf32.tf32.f32 "
        "{%0,%1,%2,%3}, {%4,%5,%6,%7}, {%8,%9}, {%10,%11,%12,%13};\n"
        : "=f"(d[0]), "=f"(d[1]), "=f"(d[2]), "=f"(d[3])
        : "r"(a[0]), "r"(a[1]), "r"(a[2]), "r"(a[3]),
          "r"(b[0]), "r"(b[1]),
          "f"(c[0]), "f"(c[1]), "f"(c[2]), "f"(c[3]));
}
// fp16 m16n8k16 with fp32 accumulate (GEMM path)
__device__ __forceinline__ void mma_fp16(float* d, const uint32_t* a,
                                         const uint32_t* b, const float* c) {
    asm volatile(
        "mma.sync.aligned.m16n8k16.row.col.f32.f16.f16.f32 "
        "{%0,%1,%2,%3}, {%4,%5,%6,%7}, {%8,%9}, {%10,%11,%12,%13};\n"
        : "=f"(d[0]), "=f"(d[1]), "=f"(d[2]), "=f"(d[3])
        : "r"(a[0]), "r"(a[1]), "r"(a[2]), "r"(a[3]),
          "r"(b[0]), "r"(b[1]),
          "f"(c[0]), "f"(c[1]), "f"(c[2]), "f"(c[3]));
}
__device__ __forceinline__ void cp16(uint32_t saddr, const void* g) {
    asm volatile("cp.async.cg.shared.global [%0], [%1], 16;\n"
                 :: "r"(saddr), "l"(g));
}
__device__ __forceinline__ void cp_commit() {
    asm volatile("cp.async.commit_group;\n" ::: "memory");
}
__device__ __forceinline__ void cp_wait0() {
    asm volatile("cp.async.wait_group 0;\n" ::: "memory");
}
__device__ __forceinline__ uint32_t s2u(const void* p) {
    return (uint32_t)__cvta_generic_to_shared(p);
}

// ---------------------------------------------------------------------------
// prep kernels
// ---------------------------------------------------------------------------
// fp16 convert-copy: 4 floats -> 2 half2 words per thread
__global__ __launch_bounds__(256) void round_fp16_kernel(
    const float4* __restrict__ src, uint2* __restrict__ dst)
{
    const int i = blockIdx.x * 256 + threadIdx.x;
    float4 v = src[i];
    dst[i] = make_uint2(packh2(v.x, v.y), packh2(v.z, v.w));
}

// pack weights [K][N] fp32 -> [K/2][N] half2 k-pair words
__global__ __launch_bounds__(256) void pack_w_fp16_kernel(
    const float* __restrict__ src, uint32_t* __restrict__ dst, int N)
{
    const int idx = blockIdx.x * 256 + threadIdx.x;
    const int kw = idx / N;
    const int n  = idx - kw * N;
    dst[idx] = packh2(src[(size_t)(2 * kw) * N + n],
                      src[(size_t)(2 * kw + 1) * N + n]);
}

// ---------------------------------------------------------------------------
// fp16 tensor-core GEMM: C[M,N] = A[M,K] @ B[K,N].
// A: fp16 natural [M][K] (half2 words, k-pairs contiguous).
// B: fp16 packed  [K/2][N] (word (kw,n) = (B[2kw][n], B[2kw+1][n])).
// 64x128x32 CTA tile, 256 threads, warp grid 2x4, cp.async double-buffered.
// ---------------------------------------------------------------------------
#define GAS 20     // A row stride (words): 16 data + 4 pad
#define GBS 136    // B kw-row stride (words): 128 data + 8 pad
#define GEMM_BM 64
#define GEMM_A_W (GEMM_BM * GAS)            // 1280
#define GEMM_B_W (16 * GBS)                 // 2176
#define GEMM_STAGE_W (GEMM_A_W + GEMM_B_W)  // 3456
#define GEMM_SMEM_BYTES (2 * GEMM_STAGE_W * 4)   // 27648

__global__ __launch_bounds__(256, 3) void gemm_fp16(
    const uint32_t* __restrict__ A, const uint32_t* __restrict__ Bp,
    float* __restrict__ C, int M, int N, int K)
{
    extern __shared__ uint32_t sh[];
    const int tid  = threadIdx.x;
    const int lane = tid & 31;
    const int wid  = tid >> 5;
    const int wm   = wid >> 2;      // 0..1 -> rows 32*wm
    const int wn   = wid & 3;       // 0..3 -> cols 32*wn
    const int lr   = lane >> 2;
    const int lc   = lane & 3;
    const int brow = blockIdx.y * GEMM_BM;
    const int bcol = blockIdx.x * 128;
    const int K2   = K >> 1;

    // cp.async coords
    const int ar = tid >> 2;              // 0..63 (A row)
    const int aw = (tid & 3) * 4;         // word within A row
    const int br = tid >> 4;              // 0..15 (B kw row)
    const int bw = (tid & 15) * 4;        // word within B row (+64 chunk 2)

    const uint32_t s_base = s2u(sh);

    float acc[2][4][4];
#pragma unroll
    for (int mf = 0; mf < 2; mf++)
#pragma unroll
        for (int nf = 0; nf < 4; nf++)
#pragma unroll
            for (int i = 0; i < 4; i++) acc[mf][nf][i] = 0.f;

    const int ntk = K >> 5;

#define GEMM_ISSUE(KT, BUF)                                                    \
    do {                                                                       \
        const int k0w = (KT) * 16;                                             \
        const uint32_t abuf = s_base + (BUF) * GEMM_STAGE_W * 4;               \
        const uint32_t bbuf = abuf + GEMM_A_W * 4;                             \
        cp16(abuf + (ar * GAS + aw) * 4,                                       \
             A + (size_t)(brow + ar) * K2 + k0w + aw);                         \
        _Pragma("unroll")                                                      \
        for (int i = 0; i < 2; i++) {                                          \
            cp16(bbuf + (br * GBS + bw + 64 * i) * 4,                          \
                 Bp + (size_t)(k0w + br) * N + bcol + bw + 64 * i);            \
        }                                                                      \
        cp_commit();                                                           \
    } while (0)

    GEMM_ISSUE(0, 0);

    for (int kt = 0; kt < ntk; kt++) {
        cp_wait0();
        __syncthreads();
        if (kt + 1 < ntk) GEMM_ISSUE(kt + 1, (kt + 1) & 1);

        const uint32_t* Ab = sh + (kt & 1) * GEMM_STAGE_W;
        const uint32_t* Bb = Ab + GEMM_A_W;

#pragma unroll
        for (int ks = 0; ks < 2; ks++) {
            const int kk = ks * 8;
            uint32_t af[2][4], bf[4][2];
#pragma unroll
            for (int mf = 0; mf < 2; mf++) {
                const int r = wm * 32 + mf * 16 + lr;
                af[mf][0] = Ab[r * GAS + kk + lc];
                af[mf][1] = Ab[(r + 8) * GAS + kk + lc];
                af[mf][2] = Ab[r * GAS + kk + lc + 4];
                af[mf][3] = Ab[(r + 8) * GAS + kk + lc + 4];
            }
#pragma unroll
            for (int nf = 0; nf < 4; nf++) {
                const int c = wn * 32 + nf * 8 + lr;
                bf[nf][0] = Bb[(kk + lc) * GBS + c];
                bf[nf][1] = Bb[(kk + lc + 4) * GBS + c];
            }
#pragma unroll
            for (int mf = 0; mf < 2; mf++)
#pragma unroll
                for (int nf = 0; nf < 4; nf++)
                    mma_fp16(acc[mf][nf], af[mf], bf[nf], acc[mf][nf]);
        }
    }

#pragma unroll
    for (int mf = 0; mf < 2; mf++)
#pragma unroll
        for (int nf = 0; nf < 4; nf++) {
            const int r = brow + wm * 32 + mf * 16 + lr;
            const int c = bcol + wn * 32 + nf * 8 + 2 * lc;
            *(float2*)(C + (size_t)r * N + c) =
                make_float2(acc[mf][nf][0], acc[mf][nf][1]);
            *(float2*)(C + (size_t)(r + 8) * N + c) =
                make_float2(acc[mf][nf][2], acc[mf][nf][3]);
        }
#undef GEMM_ISSUE
}

// ---------------------------------------------------------------------------
// mRoPE + tf32 pre-round (Q/K rotate+round, V round only) on fp32 g_qkv
// ---------------------------------------------------------------------------
__global__ void rope_kernel(const int* __restrict__ positions)
{
    const int t  = blockIdx.x;
    const int hy = blockIdx.y;          // 0..23
    const int j  = threadIdx.x;         // 0..63

    if (hy >= 20) {
        float* base = g_qkv + (size_t)t * QKV_N + V_OFF
                      + (hy - 20) * HEAD_DIM + 2 * j;
        base[0] = roundtf(base[0]);
        base[1] = roundtf(base[1]);
        return;
    }

    const int off = (hy < N_HEADS) ? hy * HEAD_DIM
                                   : K_OFF + (hy - N_HEADS) * HEAD_DIM;
    const int prow = (j >= 44) ? 0 : ((j & 1) ? 2 : 1);
    const float pos = (float)positions[prow * T_SEQ + t];
    const float inv = expf(-((float)j * (1.0f / 64.0f)) * 13.122363377404328f);
    const float ang = pos * inv;
    float sn, cs;
    sincosf(ang, &sn, &cs);

    float* base = g_qkv + (size_t)t * QKV_N + off + 2 * j;
    const float x1 = base[0];
    const float x2 = base[1];
    base[0] = roundtf(x1 * cs - x2 * sn);
    base[1] = roundtf(x2 * cs + x1 * sn);
}

// ---------------------------------------------------------------------------
// Causal flash attention (tf32 path, R6/R9-proven), epilogue -> fp16.
// Block: 128 queries x 1 head, 256 threads, 8 warps x 16 rows.
// ---------------------------------------------------------------------------
#define AKS 132
#define AVS 136
#define ATTN_SMEM_WORDS (2 * 64 * AKS + 2 * 64 * AVS)
#define ATTN_SMEM_BYTES (ATTN_SMEM_WORDS * 4)

__global__ __launch_bounds__(256) void attn_tc_kernel()
{
    extern __shared__ uint32_t sm[];
    uint32_t* Kr = sm;                 // [2][64][132]
    uint32_t* Vr = Kr + 2 * 64 * AKS;  // [2][64][136]

    const int tid  = threadIdx.x;
    const int lane = tid & 31;
    const int wid  = tid >> 5;         // 0..7 : query rows 16*wid
    const int lr   = lane >> 2;
    const int lc   = lane & 3;
    const int h    = blockIdx.y;
    const int qb   = gridDim.x - 1 - blockIdx.x;   // big tiles first
    const int kvh  = h >> 2;

    const int row0 = qb * 128 + wid * 16 + lr;

    const uint32_t kr_base = s2u(Kr);
    const uint32_t vr_base = s2u(Vr);
    const int ldr = tid >> 5;
    const int ldc = (tid & 31) * 4;

#define ATTN_ISSUE(J, BUF)                                                     \
    do {                                                                       \
        const uint32_t kb = kr_base + (BUF) * 64 * AKS * 4;                    \
        const uint32_t vb = vr_base + (BUF) * 64 * AVS * 4;                    \
        _Pragma("unroll")                                                      \
        for (int i = 0; i < 8; i++) {                                          \
            const int r = ldr + 8 * i;                                         \
            const size_t grow = (size_t)((J) * 64 + r) * QKV_N                 \
                                + kvh * HEAD_DIM + ldc;                        \
            cp16(kb + (r * AKS + ldc) * 4, g_qkv + grow + K_OFF);              \
            cp16(vb + (r * AVS + ldc) * 4, g_qkv + grow + V_OFF);              \
        }                                                                      \
        cp_commit();                                                           \
    } while (0)

    ATTN_ISSUE(0, 0);

    // ---- Q fragments straight from gmem (pre-rounded by rope) ----
    uint32_t qf[16][4];
    {
        const float* q0 = g_qkv + (size_t)row0 * QKV_N + h * HEAD_DIM;
        const float* q8 = q0 + 8 * (size_t)QKV_N;
#pragma unroll
        for (int ks = 0; ks < 16; ks++) {
            qf[ks][0] = __float_as_uint(q0[8 * ks + lc]);
            qf[ks][1] = __float_as_uint(q8[8 * ks + lc]);
            qf[ks][2] = __float_as_uint(q0[8 * ks + lc + 4]);
            qf[ks][3] = __float_as_uint(q8[8 * ks + lc + 4]);
        }
    }

    float m0 = -1e30f, m1 = -1e30f, l0 = 0.f, l1 = 0.f;
    float o[16][4];
#pragma unroll
    for (int nf = 0; nf < 16; nf++)
#pragma unroll
        for (int i = 0; i < 4; i++) o[nf][i] = 0.f;

    const float scale = 0.08838834764831844f;   // 128^-0.5
    const int jmax = 2 * qb + 1;
    const int wrow_lo = qb * 128 + wid * 16;

    for (int j = 0; j <= jmax; j++) {
        cp_wait0();
        __syncthreads();
        if (j < jmax) ATTN_ISSUE(j + 1, (j + 1) & 1);

        const bool active = (64 * j <= wrow_lo + 15);
        if (active) {
            const uint32_t* Kb = Kr + (j & 1) * 64 * AKS;
            const uint32_t* Vb = Vr + (j & 1) * 64 * AVS;

            float sc[8][4];
#pragma unroll
            for (int nf = 0; nf < 8; nf++)
#pragma unroll
                for (int i = 0; i < 4; i++) sc[nf][i] = 0.f;

#pragma unroll
            for (int ks = 0; ks < 16; ks++) {
                const int kk = ks * 8;
                uint32_t bf[8][2];
#pragma unroll
                for (int nf = 0; nf < 8; nf++) {
                    const int c = nf * 8 + lr;
                    bf[nf][0] = Kb[c * AKS + kk + lc];
                    bf[nf][1] = Kb[c * AKS + kk + lc + 4];
                }
#pragma unroll
                for (int nf = 0; nf < 8; nf++)
                    mma_tf32(sc[nf], qf[ks], bf[nf], sc[nf]);
            }

            const bool needmask = (64 * j + 63 > wrow_lo);
#pragma unroll
            for (int nf = 0; nf < 8; nf++)
#pragma unroll
                for (int ci = 0; ci < 4; ci++) {
                    float s = sc[nf][ci] * scale;
                    if (needmask) {
                        const int col = 64 * j + nf * 8 + 2 * lc + (ci & 1);
                        const int row = row0 + ((ci >> 1) * 8);
                        if (col > row) s = -1e30f;
                    }
                    sc[nf][ci] = s;
                }

            float mx0 = sc[0][0], mx1 = sc[0][2];
#pragma unroll
            for (int nf = 0; nf < 8; nf++) {
                mx0 = fmaxf(mx0, fmaxf(sc[nf][0], sc[nf][1]));
                mx1 = fmaxf(mx1, fmaxf(sc[nf][2], sc[nf][3]));
            }
            mx0 = fmaxf(mx0, __shfl_xor_sync(0xffffffffu, mx0, 1));
            mx0 = fmaxf(mx0, __shfl_xor_sync(0xffffffffu, mx0, 2));
            mx1 = fmaxf(mx1, __shfl_xor_sync(0xffffffffu, mx1, 1));
            mx1 = fmaxf(mx1, __shfl_xor_sync(0xffffffffu, mx1, 2));

            const float mn0 = fmaxf(m0, mx0);
            const float mn1 = fmaxf(m1, mx1);
            const float a0 = __expf(m0 - mn0);
            const float a1 = __expf(m1 - mn1);
            m0 = mn0; m1 = mn1;

            float ls0 = 0.f, ls1 = 0.f;
#pragma unroll
            for (int nf = 0; nf < 8; nf++) {
                sc[nf][0] = __expf(sc[nf][0] - mn0);
                sc[nf][1] = __expf(sc[nf][1] - mn0);
                sc[nf][2] = __expf(sc[nf][2] - mn1);
                sc[nf][3] = __expf(sc[nf][3] - mn1);
                ls0 += sc[nf][0] + sc[nf][1];
                ls1 += sc[nf][2] + sc[nf][3];
            }
            ls0 += __shfl_xor_sync(0xffffffffu, ls0, 1);
            ls0 += __shfl_xor_sync(0xffffffffu, ls0, 2);
            ls1 += __shfl_xor_sync(0xffffffffu, ls1, 1);
            ls1 += __shfl_xor_sync(0xffffffffu, ls1, 2);
            l0 = l0 * a0 + ls0;
            l1 = l1 * a1 + ls1;

#pragma unroll
            for (int nf = 0; nf < 16; nf++) {
                o[nf][0] *= a0; o[nf][1] *= a0;
                o[nf][2] *= a1; o[nf][3] *= a1;
            }

            const int src0 = lr * 4 + (lc >> 1);
            const int src1 = src0 + 2;
            const bool odd = (lc & 1);
#pragma unroll
            for (int ks = 0; ks < 8; ks++) {
                const float b0 = __shfl_sync(0xffffffffu, sc[ks][0], src0);
                const float b1 = __shfl_sync(0xffffffffu, sc[ks][1], src0);
                const float b2 = __shfl_sync(0xffffffffu, sc[ks][2], src0);
                const float b3 = __shfl_sync(0xffffffffu, sc[ks][3], src0);
                const float c0 = __shfl_sync(0xffffffffu, sc[ks][0], src1);
                const float c1 = __shfl_sync(0xffffffffu, sc[ks][1], src1);
                const float c2 = __shfl_sync(0xffffffffu, sc[ks][2], src1);
                const float c3 = __shfl_sync(0xffffffffu, sc[ks][3], src1);
                uint32_t pf[4];
                pf[0] = f2tf32(odd ? b1 : b0);
                pf[1] = f2tf32(odd ? b3 : b2);
                pf[2] = f2tf32(odd ? c1 : c0);
                pf[3] = f2tf32(odd ? c3 : c2);

                const int kk = ks * 8;
#pragma unroll
                for (int nf = 0; nf < 16; nf++) {
                    const int c = nf * 8 + lr;
                    uint32_t vf[2];
                    vf[0] = Vb[(kk + lc) * AVS + c];
                    vf[1] = Vb[(kk + lc + 4) * AVS + c];
                    mma_tf32(o[nf], pf, vf, o[nf]);
                }
            }
        }
    }
#undef ATTN_ISSUE

    // ---- epilogue: normalize, store fp16 (A-side of O-proj) ----
    const float i0 = 1.0f / l0;
    const float i1 = 1.0f / l1;
#pragma unroll
    for (int nf = 0; nf < 16; nf++) {
        const int cw = (h * HEAD_DIM + nf * 8 + 2 * lc) >> 1;
        g_attn_h[(size_t)row0 * (O_DIM / 2) + cw] =
            packh2(o[nf][0] * i0, o[nf][1] * i0);
        g_attn_h[(size_t)(row0 + 8) * (O_DIM / 2) + cw] =
            packh2(o[nf][2] * i1, o[nf][3] * i1);
    }
}

// ---------------------------------------------------------------------------
// Launch
// ---------------------------------------------------------------------------
extern "C" void kernel_launch(void* const* d_in, const int* in_sizes, int n_in,
                              void* d_out, int out_size)
{
    const int*   positions = (const int*)d_in[0];
    const float* hidden    = (const float*)d_in[1];
    const float* w_qkv     = (const float*)d_in[2];
    const float* w_o       = (const float*)d_in[3];
    float*       out       = (float*)d_out;

    float *qkv_ptr;
    uint32_t *attn_ptr, *hid_ptr, *wqkv_ptr, *wo_ptr;
    cudaGetSymbolAddress((void**)&qkv_ptr,  g_qkv);
    cudaGetSymbolAddress((void**)&attn_ptr, g_attn_h);
    cudaGetSymbolAddress((void**)&hid_ptr,  g_hid_h);
    cudaGetSymbolAddress((void**)&wqkv_ptr, g_wqkv_h);
    cudaGetSymbolAddress((void**)&wo_ptr,   g_wo_h);

    static int cfg = 0;
    if (!cfg) {
        cudaFuncSetAttribute(gemm_fp16,
                             cudaFuncAttributeMaxDynamicSharedMemorySize,
                             GEMM_SMEM_BYTES);
        cudaFuncSetAttribute(attn_tc_kernel,
                             cudaFuncAttributeMaxDynamicSharedMemorySize,
                             ATTN_SMEM_BYTES);
        cfg = 1;
    }

    // 0) prep: fp16 convert activations; pack weights as k-pair half2
    round_fp16_kernel<<<(T_SEQ * HIDDEN) / 1024, 256>>>(
        (const float4*)hidden, (uint2*)hid_ptr);
    pack_w_fp16_kernel<<<((HIDDEN / 2) * QKV_N) / 256, 256>>>(
        w_qkv, wqkv_ptr, QKV_N);
    pack_w_fp16_kernel<<<((O_DIM / 2) * HIDDEN) / 256, 256>>>(
        w_o, wo_ptr, HIDDEN);

    // 1) QKV projection (fp16 MMA): [2048,2048] @ [2048,3072] -> fp32
    gemm_fp16<<<dim3(QKV_N / 128, T_SEQ / GEMM_BM), 256, GEMM_SMEM_BYTES>>>(
        hid_ptr, wqkv_ptr, qkv_ptr, T_SEQ, QKV_N, HIDDEN);

    // 2) mRoPE + V rounding (tf32, in place on fp32 g_qkv)
    rope_kernel<<<dim3(T_SEQ, N_HEADS + 2 * N_KV), 64>>>(positions);

    // 3) Causal flash attention (tf32) -> fp16 output
    attn_tc_kernel<<<dim3(T_SEQ / 128, N_HEADS), 256, ATTN_SMEM_BYTES>>>();

    // 4) Output projection (fp16 MMA): [2048,2048] @ [2048,2048] -> fp32
    gemm_fp16<<<dim3(O_DIM / 128, T_SEQ / GEMM_BM), 256, GEMM_SMEM_BYTES>>>(
        attn_ptr, wo_ptr, out, T_SEQ, O_DIM, HIDDEN);
}

// round 11
// speedup vs baseline: 1.5892x; 1.2228x over previous
#include <cuda_runtime.h>
#include <cuda_fp16.h>
#include <math.h>
#include <stdint.h>
#include <string.h>

// ---------------------------------------------------------------------------
// Problem constants
// ---------------------------------------------------------------------------
#define T_SEQ   2048
#define HIDDEN  2048
#define N_HEADS 16
#define N_KV    4
#define HEAD_DIM 128
#define QKV_N   ((N_HEADS + 2 * N_KV) * HEAD_DIM)   // 3072
#define K_OFF   (N_HEADS * HEAD_DIM)                 // 2048
#define V_OFF   (K_OFF + N_KV * HEAD_DIM)            // 2560
#define O_DIM   (N_HEADS * HEAD_DIM)                 // 2048

__device__ float    g_qkv[T_SEQ * QKV_N];               // fp32 QKV (24 MB)
__device__ uint32_t g_attn_h[T_SEQ * O_DIM / 2];        // fp16 attn out
__device__ uint32_t g_hid_h[T_SEQ * HIDDEN / 2];        // fp16 hidden
__device__ uint32_t g_wqkv_h[(HIDDEN / 2) * QKV_N];     // fp16 w_qkv k-pairs
__device__ uint32_t g_wo_h[(O_DIM / 2) * HIDDEN];       // fp16 w_o   k-pairs
__device__ uint32_t g_q_h[T_SEQ * N_HEADS * 64];        // fp16 Q dim-pairs
__device__ uint32_t g_k_h[N_KV * T_SEQ * 64];           // fp16 K dim-pairs
__device__ uint32_t g_v_h[N_KV * (T_SEQ / 2) * 128];    // fp16 V key-pairs

// ---------------------------------------------------------------------------
// helpers
// ---------------------------------------------------------------------------
__device__ __forceinline__ uint32_t packh2(float a, float b) {
    __half2 h = __floats2half2_rn(a, b);
    uint32_t u; memcpy(&u, &h, 4); return u;
}
__device__ __forceinline__ void mma_fp16(float* d, const uint32_t* a,
                                         const uint32_t* b, const float* c) {
    asm volatile(
        "mma.sync.aligned.m16n8k16.row.col.f32.f16.f16.f32 "
        "{%0,%1,%2,%3}, {%4,%5,%6,%7}, {%8,%9}, {%10,%11,%12,%13};\n"
        : "=f"(d[0]), "=f"(d[1]), "=f"(d[2]), "=f"(d[3])
        : "r"(a[0]), "r"(a[1]), "r"(a[2]), "r"(a[3]),
          "r"(b[0]), "r"(b[1]),
          "f"(c[0]), "f"(c[1]), "f"(c[2]), "f"(c[3]));
}
__device__ __forceinline__ void cp16(uint32_t saddr, const void* g) {
    asm volatile("cp.async.cg.shared.global [%0], [%1], 16;\n"
                 :: "r"(saddr), "l"(g));
}
__device__ __forceinline__ void cp_commit() {
    asm volatile("cp.async.commit_group;\n" ::: "memory");
}
__device__ __forceinline__ void cp_wait0() {
    asm volatile("cp.async.wait_group 0;\n" ::: "memory");
}
__device__ __forceinline__ uint32_t s2u(const void* p) {
    return (uint32_t)__cvta_generic_to_shared(p);
}

// ---------------------------------------------------------------------------
// prep kernels
// ---------------------------------------------------------------------------
__global__ __launch_bounds__(256) void round_fp16_kernel(
    const float4* __restrict__ src, uint2* __restrict__ dst)
{
    const int i = blockIdx.x * 256 + threadIdx.x;
    float4 v = src[i];
    dst[i] = make_uint2(packh2(v.x, v.y), packh2(v.z, v.w));
}

// pack weights [K][N] fp32 -> [K/2][N] half2 k-pair words
__global__ __launch_bounds__(256) void pack_w_fp16_kernel(
    const float* __restrict__ src, uint32_t* __restrict__ dst, int N)
{
    const int idx = blockIdx.x * 256 + threadIdx.x;
    const int kw = idx / N;
    const int n  = idx - kw * N;
    dst[idx] = packh2(src[(size_t)(2 * kw) * N + n],
                      src[(size_t)(2 * kw + 1) * N + n]);
}

// pack V: word(kvh, kp, d) = (V[2kp][d], V[2kp+1][d]) fp16
__global__ __launch_bounds__(256) void pack_v_kernel()
{
    const int idx = blockIdx.x * 256 + threadIdx.x;   // < 4*1024*128
    const int kvh = idx >> 17;
    const int rem = idx & 131071;
    const int kp  = rem >> 7;
    const int d   = rem & 127;
    const size_t src = (size_t)(2 * kp) * QKV_N + V_OFF + kvh * HEAD_DIM + d;
    g_v_h[idx] = packh2(g_qkv[src], g_qkv[src + QKV_N]);
}

// ---------------------------------------------------------------------------
// fp16 tensor-core GEMM (R10 version, known-good).
// ---------------------------------------------------------------------------
#define GAS 20
#define GBS 136
#define GEMM_BM 64
#define GEMM_A_W (GEMM_BM * GAS)
#define GEMM_B_W (16 * GBS)
#define GEMM_STAGE_W (GEMM_A_W + GEMM_B_W)
#define GEMM_SMEM_BYTES (2 * GEMM_STAGE_W * 4)

__global__ __launch_bounds__(256, 3) void gemm_fp16(
    const uint32_t* __restrict__ A, const uint32_t* __restrict__ Bp,
    float* __restrict__ C, int M, int N, int K)
{
    extern __shared__ uint32_t sh[];
    const int tid  = threadIdx.x;
    const int lane = tid & 31;
    const int wid  = tid >> 5;
    const int wm   = wid >> 2;
    const int wn   = wid & 3;
    const int lr   = lane >> 2;
    const int lc   = lane & 3;
    const int brow = blockIdx.y * GEMM_BM;
    const int bcol = blockIdx.x * 128;
    const int K2   = K >> 1;

    const int ar = tid >> 2;
    const int aw = (tid & 3) * 4;
    const int br = tid >> 4;
    const int bw = (tid & 15) * 4;

    const uint32_t s_base = s2u(sh);

    float acc[2][4][4];
#pragma unroll
    for (int mf = 0; mf < 2; mf++)
#pragma unroll
        for (int nf = 0; nf < 4; nf++)
#pragma unroll
            for (int i = 0; i < 4; i++) acc[mf][nf][i] = 0.f;

    const int ntk = K >> 5;

#define GEMM_ISSUE(KT, BUF)                                                    \
    do {                                                                       \
        const int k0w = (KT) * 16;                                             \
        const uint32_t abuf = s_base + (BUF) * GEMM_STAGE_W * 4;               \
        const uint32_t bbuf = abuf + GEMM_A_W * 4;                             \
        cp16(abuf + (ar * GAS + aw) * 4,                                       \
             A + (size_t)(brow + ar) * K2 + k0w + aw);                         \
        _Pragma("unroll")                                                      \
        for (int i = 0; i < 2; i++) {                                          \
            cp16(bbuf + (br * GBS + bw + 64 * i) * 4,                          \
                 Bp + (size_t)(k0w + br) * N + bcol + bw + 64 * i);            \
        }                                                                      \
        cp_commit();                                                           \
    } while (0)

    GEMM_ISSUE(0, 0);

    for (int kt = 0; kt < ntk; kt++) {
        cp_wait0();
        __syncthreads();
        if (kt + 1 < ntk) GEMM_ISSUE(kt + 1, (kt + 1) & 1);

        const uint32_t* Ab = sh + (kt & 1) * GEMM_STAGE_W;
        const uint32_t* Bb = Ab + GEMM_A_W;

#pragma unroll
        for (int ks = 0; ks < 2; ks++) {
            const int kk = ks * 8;
            uint32_t af[2][4], bf[4][2];
#pragma unroll
            for (int mf = 0; mf < 2; mf++) {
                const int r = wm * 32 + mf * 16 + lr;
                af[mf][0] = Ab[r * GAS + kk + lc];
                af[mf][1] = Ab[(r + 8) * GAS + kk + lc];
                af[mf][2] = Ab[r * GAS + kk + lc + 4];
                af[mf][3] = Ab[(r + 8) * GAS + kk + lc + 4];
            }
#pragma unroll
            for (int nf = 0; nf < 4; nf++) {
                const int c = wn * 32 + nf * 8 + lr;
                bf[nf][0] = Bb[(kk + lc) * GBS + c];
                bf[nf][1] = Bb[(kk + lc + 4) * GBS + c];
            }
#pragma unroll
            for (int mf = 0; mf < 2; mf++)
#pragma unroll
                for (int nf = 0; nf < 4; nf++)
                    mma_fp16(acc[mf][nf], af[mf], bf[nf], acc[mf][nf]);
        }
    }

#pragma unroll
    for (int mf = 0; mf < 2; mf++)
#pragma unroll
        for (int nf = 0; nf < 4; nf++) {
            const int r = brow + wm * 32 + mf * 16 + lr;
            const int c = bcol + wn * 32 + nf * 8 + 2 * lc;
            *(float2*)(C + (size_t)r * N + c) =
                make_float2(acc[mf][nf][0], acc[mf][nf][1]);
            *(float2*)(C + (size_t)(r + 8) * N + c) =
                make_float2(acc[mf][nf][2], acc[mf][nf][3]);
        }
#undef GEMM_ISSUE
}

// ---------------------------------------------------------------------------
// mRoPE -> fp16. hy 0..15: Q heads -> g_q_h; 16..19: K heads -> g_k_h.
// Thread j owns dims (2j, 2j+1) = one half2 word.
// ---------------------------------------------------------------------------
__global__ void rope_kernel(const int* __restrict__ positions)
{
    const int t  = blockIdx.x;
    const int hy = blockIdx.y;          // 0..19
    const int j  = threadIdx.x;         // 0..63

    const int off = (hy < N_HEADS) ? hy * HEAD_DIM
                                   : K_OFF + (hy - N_HEADS) * HEAD_DIM;
    const int prow = (j >= 44) ? 0 : ((j & 1) ? 2 : 1);
    const float pos = (float)positions[prow * T_SEQ + t];
    const float inv = expf(-((float)j * (1.0f / 64.0f)) * 13.122363377404328f);
    const float ang = pos * inv;
    float sn, cs;
    sincosf(ang, &sn, &cs);

    const float* base = g_qkv + (size_t)t * QKV_N + off + 2 * j;
    const float x1 = base[0];
    const float x2 = base[1];
    const uint32_t w = packh2(x1 * cs - x2 * sn, x2 * cs + x1 * sn);

    if (hy < N_HEADS)
        g_q_h[(size_t)t * (N_HEADS * 64) + hy * 64 + j] = w;
    else
        g_k_h[(size_t)(hy - N_HEADS) * T_SEQ * 64 + (size_t)t * 64 + j] = w;
}

// ---------------------------------------------------------------------------
// Causal flash attention, full fp16 MMA (m16n8k16).
// Block: 128 queries x 1 head, 256 threads, 8 warps x 16 rows.
// K smem [64][68] dim-pair words; V smem [32][136] key-pair words.
// P: C-frag == A-frag layout -> 16 packh2 per tile, NO shuffles.
// ---------------------------------------------------------------------------
#define AKS2 68
#define AVS2 136
#define ATTN_SMEM_WORDS (2 * (64 * AKS2 + 32 * AVS2))
#define ATTN_SMEM_BYTES (ATTN_SMEM_WORDS * 4)

__global__ __launch_bounds__(256) void attn_tc_kernel()
{
    extern __shared__ uint32_t sm[];
    uint32_t* Kr = sm;                  // [2][64][68]
    uint32_t* Vr = Kr + 2 * 64 * AKS2;  // [2][32][136]

    const int tid  = threadIdx.x;
    const int lane = tid & 31;
    const int wid  = tid >> 5;          // 0..7 : query rows 16*wid
    const int lr   = lane >> 2;
    const int lc   = lane & 3;
    const int h    = blockIdx.y;
    const int qb   = gridDim.x - 1 - blockIdx.x;   // big tiles first
    const int kvh  = h >> 2;

    const int row0 = qb * 128 + wid * 16 + lr;

    const uint32_t kr_base = s2u(Kr);
    const uint32_t vr_base = s2u(Vr);

    const uint32_t* Kg = g_k_h + (size_t)kvh * T_SEQ * 64;
    const uint32_t* Vg = g_v_h + (size_t)kvh * (T_SEQ / 2) * 128;

#define ATTN_ISSUE(J, BUF)                                                     \
    do {                                                                       \
        const uint32_t kb = kr_base + (BUF) * 64 * AKS2 * 4;                   \
        const uint32_t vb = vr_base + (BUF) * 32 * AVS2 * 4;                   \
        _Pragma("unroll")                                                      \
        for (int i = 0; i < 4; i++) {                                          \
            const int id = tid + 256 * i;                                      \
            const int kr = id >> 4;                                            \
            const int kw = (id & 15) * 4;                                      \
            cp16(kb + (kr * AKS2 + kw) * 4,                                    \
                 Kg + (size_t)((J) * 64 + kr) * 64 + kw);                      \
            const int vr = id >> 5;                                            \
            const int vw = (id & 31) * 4;                                      \
            cp16(vb + (vr * AVS2 + vw) * 4,                                    \
                 Vg + (size_t)((J) * 32 + vr) * 128 + vw);                     \
        }                                                                      \
        cp_commit();                                                           \
    } while (0)

    ATTN_ISSUE(0, 0);

    // ---- Q fragments from gmem fp16 (8 k-groups of 16 dims) ----
    uint32_t qf[8][4];
    {
        const uint32_t* q0 = g_q_h + (size_t)row0 * (N_HEADS * 64) + h * 64;
        const uint32_t* q8 = q0 + 8 * (size_t)(N_HEADS * 64);
#pragma unroll
        for (int ks = 0; ks < 8; ks++) {
            qf[ks][0] = q0[8 * ks + lc];
            qf[ks][1] = q8[8 * ks + lc];
            qf[ks][2] = q0[8 * ks + lc + 4];
            qf[ks][3] = q8[8 * ks + lc + 4];
        }
    }

    float m0 = -1e30f, m1 = -1e30f, l0 = 0.f, l1 = 0.f;
    float o[16][4];
#pragma unroll
    for (int nf = 0; nf < 16; nf++)
#pragma unroll
        for (int i = 0; i < 4; i++) o[nf][i] = 0.f;

    const float scale = 0.08838834764831844f;   // 128^-0.5
    const int jmax = 2 * qb + 1;
    const int wrow_lo = qb * 128 + wid * 16;

    for (int j = 0; j <= jmax; j++) {
        cp_wait0();
        __syncthreads();
        if (j < jmax) ATTN_ISSUE(j + 1, (j + 1) & 1);

        const bool active = (64 * j <= wrow_lo + 15);
        if (active) {
            const uint32_t* Kb = Kr + (j & 1) * 64 * AKS2;
            const uint32_t* Vb = Vr + (j & 1) * 32 * AVS2;

            // ---- scores = Q @ K^T : warp tile 16 x 64 ----
            float sc[8][4];
#pragma unroll
            for (int nf = 0; nf < 8; nf++)
#pragma unroll
                for (int i = 0; i < 4; i++) sc[nf][i] = 0.f;

#pragma unroll
            for (int ks = 0; ks < 8; ks++) {
                const int kk = ks * 8;
                uint32_t bf[8][2];
#pragma unroll
                for (int nf = 0; nf < 8; nf++) {
                    const int c = nf * 8 + lr;
                    bf[nf][0] = Kb[c * AKS2 + kk + lc];
                    bf[nf][1] = Kb[c * AKS2 + kk + lc + 4];
                }
#pragma unroll
                for (int nf = 0; nf < 8; nf++)
                    mma_fp16(sc[nf], qf[ks], bf[nf], sc[nf]);
            }

            // ---- scale + causal mask ----
            const bool needmask = (64 * j + 63 > wrow_lo);
#pragma unroll
            for (int nf = 0; nf < 8; nf++)
#pragma unroll
                for (int ci = 0; ci < 4; ci++) {
                    float s = sc[nf][ci] * scale;
                    if (needmask) {
                        const int col = 64 * j + nf * 8 + 2 * lc + (ci & 1);
                        const int row = row0 + ((ci >> 1) * 8);
                        if (col > row) s = -1e30f;
                    }
                    sc[nf][ci] = s;
                }

            // ---- warp-local row max ----
            float mx0 = sc[0][0], mx1 = sc[0][2];
#pragma unroll
            for (int nf = 0; nf < 8; nf++) {
                mx0 = fmaxf(mx0, fmaxf(sc[nf][0], sc[nf][1]));
                mx1 = fmaxf(mx1, fmaxf(sc[nf][2], sc[nf][3]));
            }
            mx0 = fmaxf(mx0, __shfl_xor_sync(0xffffffffu, mx0, 1));
            mx0 = fmaxf(mx0, __shfl_xor_sync(0xffffffffu, mx0, 2));
            mx1 = fmaxf(mx1, __shfl_xor_sync(0xffffffffu, mx1, 1));
            mx1 = fmaxf(mx1, __shfl_xor_sync(0xffffffffu, mx1, 2));

            const float mn0 = fmaxf(m0, mx0);
            const float mn1 = fmaxf(m1, mx1);
            const float a0 = __expf(m0 - mn0);
            const float a1 = __expf(m1 - mn1);
            m0 = mn0; m1 = mn1;

            // ---- p = exp(s - m); row sums ----
            float ls0 = 0.f, ls1 = 0.f;
#pragma unroll
            for (int nf = 0; nf < 8; nf++) {
                sc[nf][0] = __expf(sc[nf][0] - mn0);
                sc[nf][1] = __expf(sc[nf][1] - mn0);
                sc[nf][2] = __expf(sc[nf][2] - mn1);
                sc[nf][3] = __expf(sc[nf][3] - mn1);
                ls0 += sc[nf][0] + sc[nf][1];
                ls1 += sc[nf][2] + sc[nf][3];
            }
            ls0 += __shfl_xor_sync(0xffffffffu, ls0, 1);
            ls0 += __shfl_xor_sync(0xffffffffu, ls0, 2);
            ls1 += __shfl_xor_sync(0xffffffffu, ls1, 1);
            ls1 += __shfl_xor_sync(0xffffffffu, ls1, 2);
            l0 = l0 * a0 + ls0;
            l1 = l1 * a1 + ls1;

            // ---- rescale output accumulators ----
#pragma unroll
            for (int nf = 0; nf < 16; nf++) {
                o[nf][0] *= a0; o[nf][1] *= a0;
                o[nf][2] *= a1; o[nf][3] *= a1;
            }

            // ---- PV: pack P (C-frag == A-frag), fp16 MMA ----
#pragma unroll
            for (int ks = 0; ks < 4; ks++) {
                uint32_t pf[4];
                pf[0] = packh2(sc[2 * ks][0],     sc[2 * ks][1]);
                pf[1] = packh2(sc[2 * ks][2],     sc[2 * ks][3]);
                pf[2] = packh2(sc[2 * ks + 1][0], sc[2 * ks + 1][1]);
                pf[3] = packh2(sc[2 * ks + 1][2], sc[2 * ks + 1][3]);

                const int kk = ks * 8;   // key-pair row base
#pragma unroll
                for (int nf = 0; nf < 16; nf++) {
                    const int c = nf * 8 + lr;
                    uint32_t vf[2];
                    vf[0] = Vb[(kk + lc) * AVS2 + c];
                    vf[1] = Vb[(kk + lc + 4) * AVS2 + c];
                    mma_fp16(o[nf], pf, vf, o[nf]);
                }
            }
        }
    }
#undef ATTN_ISSUE

    // ---- epilogue: normalize, store fp16 (A-side of O-proj) ----
    const float i0 = 1.0f / l0;
    const float i1 = 1.0f / l1;
#pragma unroll
    for (int nf = 0; nf < 16; nf++) {
        const int cw = (h * HEAD_DIM + nf * 8 + 2 * lc) >> 1;
        g_attn_h[(size_t)row0 * (O_DIM / 2) + cw] =
            packh2(o[nf][0] * i0, o[nf][1] * i0);
        g_attn_h[(size_t)(row0 + 8) * (O_DIM / 2) + cw] =
            packh2(o[nf][2] * i1, o[nf][3] * i1);
    }
}

// ---------------------------------------------------------------------------
// Launch
// ---------------------------------------------------------------------------
extern "C" void kernel_launch(void* const* d_in, const int* in_sizes, int n_in,
                              void* d_out, int out_size)
{
    const int*   positions = (const int*)d_in[0];
    const float* hidden    = (const float*)d_in[1];
    const float* w_qkv     = (const float*)d_in[2];
    const float* w_o       = (const float*)d_in[3];
    float*       out       = (float*)d_out;

    float *qkv_ptr;
    uint32_t *attn_ptr, *hid_ptr, *wqkv_ptr, *wo_ptr;
    cudaGetSymbolAddress((void**)&qkv_ptr,  g_qkv);
    cudaGetSymbolAddress((void**)&attn_ptr, g_attn_h);
    cudaGetSymbolAddress((void**)&hid_ptr,  g_hid_h);
    cudaGetSymbolAddress((void**)&wqkv_ptr, g_wqkv_h);
    cudaGetSymbolAddress((void**)&wo_ptr,   g_wo_h);

    static int cfg = 0;
    if (!cfg) {
        cudaFuncSetAttribute(gemm_fp16,
                             cudaFuncAttributeMaxDynamicSharedMemorySize,
                             GEMM_SMEM_BYTES);
        cudaFuncSetAttribute(attn_tc_kernel,
                             cudaFuncAttributeMaxDynamicSharedMemorySize,
                             ATTN_SMEM_BYTES);
        cfg = 1;
    }

    // 0) prep: fp16 convert activations; pack weights as k-pair half2
    round_fp16_kernel<<<(T_SEQ * HIDDEN) / 1024, 256>>>(
        (const float4*)hidden, (uint2*)hid_ptr);
    pack_w_fp16_kernel<<<((HIDDEN / 2) * QKV_N) / 256, 256>>>(
        w_qkv, wqkv_ptr, QKV_N);
    pack_w_fp16_kernel<<<((O_DIM / 2) * HIDDEN) / 256, 256>>>(
        w_o, wo_ptr, HIDDEN);

    // 1) QKV projection (fp16 MMA) -> fp32 g_qkv
    gemm_fp16<<<dim3(QKV_N / 128, T_SEQ / GEMM_BM), 256, GEMM_SMEM_BYTES>>>(
        hid_ptr, wqkv_ptr, qkv_ptr, T_SEQ, QKV_N, HIDDEN);

    // 2) mRoPE -> fp16 Q/K buffers; pack fp16 V key-pairs
    rope_kernel<<<dim3(T_SEQ, N_HEADS + N_KV), 64>>>(positions);
    pack_v_kernel<<<(N_KV * (T_SEQ / 2) * 128) / 256, 256>>>();

    // 3) Causal flash attention (full fp16 MMA) -> fp16 output
    attn_tc_kernel<<<dim3(T_SEQ / 128, N_HEADS), 256, ATTN_SMEM_BYTES>>>();

    // 4) Output projection (fp16 MMA) -> fp32 out
    gemm_fp16<<<dim3(O_DIM / 128, T_SEQ / GEMM_BM), 256, GEMM_SMEM_BYTES>>>(
        attn_ptr, wo_ptr, out, T_SEQ, O_DIM, HIDDEN);
}

// round 12
// speedup vs baseline: 1.7014x; 1.0706x over previous
#include <cuda_runtime.h>
#include <cuda_fp16.h>
#include <math.h>
#include <stdint.h>
#include <string.h>

// ---------------------------------------------------------------------------
// Problem constants
// ---------------------------------------------------------------------------
#define T_SEQ   2048
#define HIDDEN  2048
#define N_HEADS 16
#define N_KV    4
#define HEAD_DIM 128
#define QKV_N   ((N_HEADS + 2 * N_KV) * HEAD_DIM)   // 3072
#define O_DIM   (N_HEADS * HEAD_DIM)                 // 2048

__device__ uint32_t g_attn_h[T_SEQ * O_DIM / 2];        // fp16 attn out
__device__ uint32_t g_hid_h[T_SEQ * HIDDEN / 2];        // fp16 hidden
__device__ uint32_t g_wqkv_h[(HIDDEN / 2) * QKV_N];     // fp16 w_qkv k-pairs
__device__ uint32_t g_wo_h[(O_DIM / 2) * HIDDEN];       // fp16 w_o   k-pairs
__device__ uint32_t g_q_h[T_SEQ * N_HEADS * 64];        // fp16 Q dim-pairs
__device__ uint32_t g_k_h[N_KV * T_SEQ * 64];           // fp16 K dim-pairs
__device__ uint32_t g_v_raw[N_KV * T_SEQ * 64];         // fp16 V dim-pairs
__device__ uint32_t g_v_h[N_KV * (T_SEQ / 2) * 128];    // fp16 V key-pairs

// ---------------------------------------------------------------------------
// helpers
// ---------------------------------------------------------------------------
__device__ __forceinline__ uint32_t packh2(float a, float b) {
    __half2 h = __floats2half2_rn(a, b);
    uint32_t u; memcpy(&u, &h, 4); return u;
}
__device__ __forceinline__ void mma_fp16(float* d, const uint32_t* a,
                                         const uint32_t* b, const float* c) {
    asm volatile(
        "mma.sync.aligned.m16n8k16.row.col.f32.f16.f16.f32 "
        "{%0,%1,%2,%3}, {%4,%5,%6,%7}, {%8,%9}, {%10,%11,%12,%13};\n"
        : "=f"(d[0]), "=f"(d[1]), "=f"(d[2]), "=f"(d[3])
        : "r"(a[0]), "r"(a[1]), "r"(a[2]), "r"(a[3]),
          "r"(b[0]), "r"(b[1]),
          "f"(c[0]), "f"(c[1]), "f"(c[2]), "f"(c[3]));
}
__device__ __forceinline__ void cp16(uint32_t saddr, const void* g) {
    asm volatile("cp.async.cg.shared.global [%0], [%1], 16;\n"
                 :: "r"(saddr), "l"(g));
}
__device__ __forceinline__ void cp_commit() {
    asm volatile("cp.async.commit_group;\n" ::: "memory");
}
__device__ __forceinline__ void cp_wait0() {
    asm volatile("cp.async.wait_group 0;\n" ::: "memory");
}
__device__ __forceinline__ uint32_t s2u(const void* p) {
    return (uint32_t)__cvta_generic_to_shared(p);
}

// ---------------------------------------------------------------------------
// prep kernels
// ---------------------------------------------------------------------------
__global__ __launch_bounds__(256) void round_fp16_kernel(
    const float4* __restrict__ src, uint2* __restrict__ dst)
{
    const int i = blockIdx.x * 256 + threadIdx.x;
    float4 v = src[i];
    dst[i] = make_uint2(packh2(v.x, v.y), packh2(v.z, v.w));
}

// pack weights [K][N] fp32 -> [K/2][N] half2 k-pair words
__global__ __launch_bounds__(256) void pack_w_fp16_kernel(
    const float* __restrict__ src, uint32_t* __restrict__ dst, int N)
{
    const int idx = blockIdx.x * 256 + threadIdx.x;
    const int kw = idx / N;
    const int n  = idx - kw * N;
    dst[idx] = packh2(src[(size_t)(2 * kw) * N + n],
                      src[(size_t)(2 * kw + 1) * N + n]);
}

// transpose fp16 V dim-pairs -> key-pair words.
// out word(kvh, kp, d) = (V[2kp][d], V[2kp+1][d]); thread handles one dim-pair.
__global__ __launch_bounds__(256) void pack_v_kernel()
{
    const int idx = blockIdx.x * 256 + threadIdx.x;   // < 4*1024*64
    const int kvh = idx >> 16;
    const int rem = idx & 65535;
    const int kp  = rem >> 6;
    const int dw  = rem & 63;
    const uint32_t w0 = g_v_raw[((size_t)kvh * T_SEQ + 2 * kp) * 64 + dw];
    const uint32_t w1 = g_v_raw[((size_t)kvh * T_SEQ + 2 * kp + 1) * 64 + dw];
    __half2 h0, h1; memcpy(&h0, &w0, 4); memcpy(&h1, &w1, 4);
    __half2 lo = __lows2half2(h0, h1);    // (V[2kp][2dw],   V[2kp+1][2dw])
    __half2 hi = __highs2half2(h0, h1);   // (V[2kp][2dw+1], V[2kp+1][2dw+1])
    uint32_t ulo, uhi; memcpy(&ulo, &lo, 4); memcpy(&uhi, &hi, 4);
    *(uint2*)&g_v_h[(size_t)kvh * (T_SEQ / 2) * 128 + kp * 128 + 2 * dw] =
        make_uint2(ulo, uhi);
}

// ---------------------------------------------------------------------------
// fp16 GEMM mainloop macro pieces (shared by both GEMM kernels)
// ---------------------------------------------------------------------------
#define GAS 20
#define GBS 136
#define GEMM_BM 64
#define GEMM_A_W (GEMM_BM * GAS)
#define GEMM_B_W (16 * GBS)
#define GEMM_STAGE_W (GEMM_A_W + GEMM_B_W)
#define GEMM_SMEM_BYTES (2 * GEMM_STAGE_W * 4)

#define GEMM_PROLOGUE()                                                        \
    extern __shared__ uint32_t sh[];                                           \
    const int tid  = threadIdx.x;                                              \
    const int lane = tid & 31;                                                 \
    const int wid  = tid >> 5;                                                 \
    const int wm   = wid >> 2;                                                 \
    const int wn   = wid & 3;                                                  \
    const int lr   = lane >> 2;                                                \
    const int lc   = lane & 3;                                                 \
    const int brow = blockIdx.y * GEMM_BM;                                     \
    const int bcol = blockIdx.x * 128;                                         \
    const int K2   = K >> 1;                                                   \
    const int ar = tid >> 2;                                                   \
    const int aw = (tid & 3) * 4;                                              \
    const int br = tid >> 4;                                                   \
    const int bw = (tid & 15) * 4;                                             \
    const uint32_t s_base = s2u(sh);                                           \
    float acc[2][4][4];                                                        \
    _Pragma("unroll")                                                          \
    for (int mf = 0; mf < 2; mf++)                                             \
        _Pragma("unroll")                                                      \
        for (int nf = 0; nf < 4; nf++)                                         \
            _Pragma("unroll")                                                  \
            for (int i = 0; i < 4; i++) acc[mf][nf][i] = 0.f;                  \
    const int ntk = K >> 5;

#define GEMM_ISSUE(KT, BUF)                                                    \
    do {                                                                       \
        const int k0w = (KT) * 16;                                             \
        const uint32_t abuf = s_base + (BUF) * GEMM_STAGE_W * 4;               \
        const uint32_t bbuf = abuf + GEMM_A_W * 4;                             \
        cp16(abuf + (ar * GAS + aw) * 4,                                       \
             A + (size_t)(brow + ar) * K2 + k0w + aw);                         \
        _Pragma("unroll")                                                      \
        for (int i = 0; i < 2; i++) {                                          \
            cp16(bbuf + (br * GBS + bw + 64 * i) * 4,                          \
                 Bp + (size_t)(k0w + br) * N + bcol + bw + 64 * i);            \
        }                                                                      \
        cp_commit();                                                           \
    } while (0)

#define GEMM_MAINLOOP()                                                        \
    GEMM_ISSUE(0, 0);                                                          \
    for (int kt = 0; kt < ntk; kt++) {                                         \
        cp_wait0();                                                            \
        __syncthreads();                                                       \
        if (kt + 1 < ntk) GEMM_ISSUE(kt + 1, (kt + 1) & 1);                    \
        const uint32_t* Ab = sh + (kt & 1) * GEMM_STAGE_W;                     \
        const uint32_t* Bb = Ab + GEMM_A_W;                                    \
        _Pragma("unroll")                                                      \
        for (int ks = 0; ks < 2; ks++) {                                       \
            const int kk = ks * 8;                                             \
            uint32_t af[2][4], bf[4][2];                                       \
            _Pragma("unroll")                                                  \
            for (int mf = 0; mf < 2; mf++) {                                   \
                const int r = wm * 32 + mf * 16 + lr;                          \
                af[mf][0] = Ab[r * GAS + kk + lc];                             \
                af[mf][1] = Ab[(r + 8) * GAS + kk + lc];                       \
                af[mf][2] = Ab[r * GAS + kk + lc + 4];                         \
                af[mf][3] = Ab[(r + 8) * GAS + kk + lc + 4];                   \
            }                                                                  \
            _Pragma("unroll")                                                  \
            for (int nf = 0; nf < 4; nf++) {                                   \
                const int c = wn * 32 + nf * 8 + lr;                           \
                bf[nf][0] = Bb[(kk + lc) * GBS + c];                           \
                bf[nf][1] = Bb[(kk + lc + 4) * GBS + c];                       \
            }                                                                  \
            _Pragma("unroll")                                                  \
            for (int mf = 0; mf < 2; mf++)                                     \
                _Pragma("unroll")                                              \
                for (int nf = 0; nf < 4; nf++)                                 \
                    mma_fp16(acc[mf][nf], af[mf], bf[nf], acc[mf][nf]);        \
        }                                                                      \
    }

// ---------------------------------------------------------------------------
// O-proj GEMM: fp32 C output
// ---------------------------------------------------------------------------
__global__ __launch_bounds__(256, 3) void gemm_fp16(
    const uint32_t* __restrict__ A, const uint32_t* __restrict__ Bp,
    float* __restrict__ C, int M, int N, int K)
{
    GEMM_PROLOGUE();
    GEMM_MAINLOOP();

#pragma unroll
    for (int mf = 0; mf < 2; mf++)
#pragma unroll
        for (int nf = 0; nf < 4; nf++) {
            const int r = brow + wm * 32 + mf * 16 + lr;
            const int c = bcol + wn * 32 + nf * 8 + 2 * lc;
            *(float2*)(C + (size_t)r * N + c) =
                make_float2(acc[mf][nf][0], acc[mf][nf][1]);
            *(float2*)(C + (size_t)(r + 8) * N + c) =
                make_float2(acc[mf][nf][2], acc[mf][nf][3]);
        }
}

// ---------------------------------------------------------------------------
// QKV GEMM with fused mRoPE epilogue. Each 128-col block = one head:
// blocks 0..15 Q (rope), 16..19 K (rope), 20..23 V (plain fp16).
// acc pairs (cols 2lc, 2lc+1) ARE the interleaved rotation pairs.
// ---------------------------------------------------------------------------
__global__ __launch_bounds__(256, 3) void gemm_fp16_qkv(
    const uint32_t* __restrict__ A, const uint32_t* __restrict__ Bp,
    const int* __restrict__ positions, int M, int N, int K)
{
    GEMM_PROLOGUE();
    GEMM_MAINLOOP();

    const int hb = blockIdx.x;   // head block 0..23

    if (hb >= 20) {              // V: fp16 dim-pair store, no rope
        uint32_t* vout = g_v_raw + (size_t)(hb - 20) * T_SEQ * 64;
#pragma unroll
        for (int mf = 0; mf < 2; mf++)
#pragma unroll
            for (int nf = 0; nf < 4; nf++) {
                const int r = brow + wm * 32 + mf * 16 + lr;
                const int j = wn * 16 + nf * 4 + lc;
                vout[(size_t)r * 64 + j] = packh2(acc[mf][nf][0], acc[mf][nf][1]);
                vout[(size_t)(r + 8) * 64 + j] = packh2(acc[mf][nf][2], acc[mf][nf][3]);
            }
        return;
    }

    // Q or K: rope rotate each pair then store fp16
    const bool isq = (hb < N_HEADS);
#pragma unroll
    for (int nf = 0; nf < 4; nf++) {
        const int j = wn * 16 + nf * 4 + lc;     // dim-pair index 0..63
        const int prow = (j >= 44) ? 0 : ((j & 1) ? 2 : 1);
        const float inv = expf(-((float)j * (1.0f / 64.0f)) * 13.122363377404328f);
#pragma unroll
        for (int mf = 0; mf < 2; mf++)
#pragma unroll
            for (int half = 0; half < 2; half++) {
                const int r = brow + wm * 32 + mf * 16 + lr + half * 8;
                const float pos = (float)positions[prow * T_SEQ + r];
                float sn, cs;
                sincosf(pos * inv, &sn, &cs);
                const float x1 = acc[mf][nf][2 * half];
                const float x2 = acc[mf][nf][2 * half + 1];
                const uint32_t w = packh2(x1 * cs - x2 * sn, x2 * cs + x1 * sn);
                if (isq)
                    g_q_h[(size_t)r * (N_HEADS * 64) + hb * 64 + j] = w;
                else
                    g_k_h[(size_t)(hb - N_HEADS) * T_SEQ * 64 + (size_t)r * 64 + j] = w;
            }
    }
}

// ---------------------------------------------------------------------------
// Causal flash attention, full fp16 MMA (R11 version, known-good).
// ---------------------------------------------------------------------------
#define AKS2 68
#define AVS2 136
#define ATTN_SMEM_WORDS (2 * (64 * AKS2 + 32 * AVS2))
#define ATTN_SMEM_BYTES (ATTN_SMEM_WORDS * 4)

__global__ __launch_bounds__(256) void attn_tc_kernel()
{
    extern __shared__ uint32_t sm[];
    uint32_t* Kr = sm;                  // [2][64][68]
    uint32_t* Vr = Kr + 2 * 64 * AKS2;  // [2][32][136]

    const int tid  = threadIdx.x;
    const int lane = tid & 31;
    const int wid  = tid >> 5;          // 0..7 : query rows 16*wid
    const int lr   = lane >> 2;
    const int lc   = lane & 3;
    const int h    = blockIdx.y;
    const int qb   = gridDim.x - 1 - blockIdx.x;   // big tiles first
    const int kvh  = h >> 2;

    const int row0 = qb * 128 + wid * 16 + lr;

    const uint32_t kr_base = s2u(Kr);
    const uint32_t vr_base = s2u(Vr);

    const uint32_t* Kg = g_k_h + (size_t)kvh * T_SEQ * 64;
    const uint32_t* Vg = g_v_h + (size_t)kvh * (T_SEQ / 2) * 128;

#define ATTN_ISSUE(J, BUF)                                                     \
    do {                                                                       \
        const uint32_t kb = kr_base + (BUF) * 64 * AKS2 * 4;                   \
        const uint32_t vb = vr_base + (BUF) * 32 * AVS2 * 4;                   \
        _Pragma("unroll")                                                      \
        for (int i = 0; i < 4; i++) {                                          \
            const int id = tid + 256 * i;                                      \
            const int kr = id >> 4;                                            \
            const int kw = (id & 15) * 4;                                      \
            cp16(kb + (kr * AKS2 + kw) * 4,                                    \
                 Kg + (size_t)((J) * 64 + kr) * 64 + kw);                      \
            const int vr = id >> 5;                                            \
            const int vw = (id & 31) * 4;                                      \
            cp16(vb + (vr * AVS2 + vw) * 4,                                    \
                 Vg + (size_t)((J) * 32 + vr) * 128 + vw);                     \
        }                                                                      \
        cp_commit();                                                           \
    } while (0)

    ATTN_ISSUE(0, 0);

    uint32_t qf[8][4];
    {
        const uint32_t* q0 = g_q_h + (size_t)row0 * (N_HEADS * 64) + h * 64;
        const uint32_t* q8 = q0 + 8 * (size_t)(N_HEADS * 64);
#pragma unroll
        for (int ks = 0; ks < 8; ks++) {
            qf[ks][0] = q0[8 * ks + lc];
            qf[ks][1] = q8[8 * ks + lc];
            qf[ks][2] = q0[8 * ks + lc + 4];
            qf[ks][3] = q8[8 * ks + lc + 4];
        }
    }

    float m0 = -1e30f, m1 = -1e30f, l0 = 0.f, l1 = 0.f;
    float o[16][4];
#pragma unroll
    for (int nf = 0; nf < 16; nf++)
#pragma unroll
        for (int i = 0; i < 4; i++) o[nf][i] = 0.f;

    const float scale = 0.08838834764831844f;   // 128^-0.5
    const int jmax = 2 * qb + 1;
    const int wrow_lo = qb * 128 + wid * 16;

    for (int j = 0; j <= jmax; j++) {
        cp_wait0();
        __syncthreads();
        if (j < jmax) ATTN_ISSUE(j + 1, (j + 1) & 1);

        const bool active = (64 * j <= wrow_lo + 15);
        if (active) {
            const uint32_t* Kb = Kr + (j & 1) * 64 * AKS2;
            const uint32_t* Vb = Vr + (j & 1) * 32 * AVS2;

            float sc[8][4];
#pragma unroll
            for (int nf = 0; nf < 8; nf++)
#pragma unroll
                for (int i = 0; i < 4; i++) sc[nf][i] = 0.f;

#pragma unroll
            for (int ks = 0; ks < 8; ks++) {
                const int kk = ks * 8;
                uint32_t bf[8][2];
#pragma unroll
                for (int nf = 0; nf < 8; nf++) {
                    const int c = nf * 8 + lr;
                    bf[nf][0] = Kb[c * AKS2 + kk + lc];
                    bf[nf][1] = Kb[c * AKS2 + kk + lc + 4];
                }
#pragma unroll
                for (int nf = 0; nf < 8; nf++)
                    mma_fp16(sc[nf], qf[ks], bf[nf], sc[nf]);
            }

            const bool needmask = (64 * j + 63 > wrow_lo);
#pragma unroll
            for (int nf = 0; nf < 8; nf++)
#pragma unroll
                for (int ci = 0; ci < 4; ci++) {
                    float s = sc[nf][ci] * scale;
                    if (needmask) {
                        const int col = 64 * j + nf * 8 + 2 * lc + (ci & 1);
                        const int row = row0 + ((ci >> 1) * 8);
                        if (col > row) s = -1e30f;
                    }
                    sc[nf][ci] = s;
                }

            float mx0 = sc[0][0], mx1 = sc[0][2];
#pragma unroll
            for (int nf = 0; nf < 8; nf++) {
                mx0 = fmaxf(mx0, fmaxf(sc[nf][0], sc[nf][1]));
                mx1 = fmaxf(mx1, fmaxf(sc[nf][2], sc[nf][3]));
            }
            mx0 = fmaxf(mx0, __shfl_xor_sync(0xffffffffu, mx0, 1));
            mx0 = fmaxf(mx0, __shfl_xor_sync(0xffffffffu, mx0, 2));
            mx1 = fmaxf(mx1, __shfl_xor_sync(0xffffffffu, mx1, 1));
            mx1 = fmaxf(mx1, __shfl_xor_sync(0xffffffffu, mx1, 2));

            const float mn0 = fmaxf(m0, mx0);
            const float mn1 = fmaxf(m1, mx1);
            const float a0 = __expf(m0 - mn0);
            const float a1 = __expf(m1 - mn1);
            m0 = mn0; m1 = mn1;

            float ls0 = 0.f, ls1 = 0.f;
#pragma unroll
            for (int nf = 0; nf < 8; nf++) {
                sc[nf][0] = __expf(sc[nf][0] - mn0);
                sc[nf][1] = __expf(sc[nf][1] - mn0);
                sc[nf][2] = __expf(sc[nf][2] - mn1);
                sc[nf][3] = __expf(sc[nf][3] - mn1);
                ls0 += sc[nf][0] + sc[nf][1];
                ls1 += sc[nf][2] + sc[nf][3];
            }
            ls0 += __shfl_xor_sync(0xffffffffu, ls0, 1);
            ls0 += __shfl_xor_sync(0xffffffffu, ls0, 2);
            ls1 += __shfl_xor_sync(0xffffffffu, ls1, 1);
            ls1 += __shfl_xor_sync(0xffffffffu, ls1, 2);
            l0 = l0 * a0 + ls0;
            l1 = l1 * a1 + ls1;

#pragma unroll
            for (int nf = 0; nf < 16; nf++) {
                o[nf][0] *= a0; o[nf][1] *= a0;
                o[nf][2] *= a1; o[nf][3] *= a1;
            }

            // PV: C-frag == A-frag, pack only
#pragma unroll
            for (int ks = 0; ks < 4; ks++) {
                uint32_t pf[4];
                pf[0] = packh2(sc[2 * ks][0],     sc[2 * ks][1]);
                pf[1] = packh2(sc[2 * ks][2],     sc[2 * ks][3]);
                pf[2] = packh2(sc[2 * ks + 1][0], sc[2 * ks + 1][1]);
                pf[3] = packh2(sc[2 * ks + 1][2], sc[2 * ks + 1][3]);

                const int kk = ks * 8;
#pragma unroll
                for (int nf = 0; nf < 16; nf++) {
                    const int c = nf * 8 + lr;
                    uint32_t vf[2];
                    vf[0] = Vb[(kk + lc) * AVS2 + c];
                    vf[1] = Vb[(kk + lc + 4) * AVS2 + c];
                    mma_fp16(o[nf], pf, vf, o[nf]);
                }
            }
        }
    }
#undef ATTN_ISSUE

    const float i0 = 1.0f / l0;
    const float i1 = 1.0f / l1;
#pragma unroll
    for (int nf = 0; nf < 16; nf++) {
        const int cw = (h * HEAD_DIM + nf * 8 + 2 * lc) >> 1;
        g_attn_h[(size_t)row0 * (O_DIM / 2) + cw] =
            packh2(o[nf][0] * i0, o[nf][1] * i0);
        g_attn_h[(size_t)(row0 + 8) * (O_DIM / 2) + cw] =
            packh2(o[nf][2] * i1, o[nf][3] * i1);
    }
}

// ---------------------------------------------------------------------------
// Launch
// ---------------------------------------------------------------------------
extern "C" void kernel_launch(void* const* d_in, const int* in_sizes, int n_in,
                              void* d_out, int out_size)
{
    const int*   positions = (const int*)d_in[0];
    const float* hidden    = (const float*)d_in[1];
    const float* w_qkv     = (const float*)d_in[2];
    const float* w_o       = (const float*)d_in[3];
    float*       out       = (float*)d_out;

    uint32_t *attn_ptr, *hid_ptr, *wqkv_ptr, *wo_ptr;
    cudaGetSymbolAddress((void**)&attn_ptr, g_attn_h);
    cudaGetSymbolAddress((void**)&hid_ptr,  g_hid_h);
    cudaGetSymbolAddress((void**)&wqkv_ptr, g_wqkv_h);
    cudaGetSymbolAddress((void**)&wo_ptr,   g_wo_h);

    static int cfg = 0;
    if (!cfg) {
        cudaFuncSetAttribute(gemm_fp16,
                             cudaFuncAttributeMaxDynamicSharedMemorySize,
                             GEMM_SMEM_BYTES);
        cudaFuncSetAttribute(gemm_fp16_qkv,
                             cudaFuncAttributeMaxDynamicSharedMemorySize,
                             GEMM_SMEM_BYTES);
        cudaFuncSetAttribute(attn_tc_kernel,
                             cudaFuncAttributeMaxDynamicSharedMemorySize,
                             ATTN_SMEM_BYTES);
        cfg = 1;
    }

    // 0) prep: fp16 convert activations; pack weights as k-pair half2
    round_fp16_kernel<<<(T_SEQ * HIDDEN) / 1024, 256>>>(
        (const float4*)hidden, (uint2*)hid_ptr);
    pack_w_fp16_kernel<<<((HIDDEN / 2) * QKV_N) / 256, 256>>>(
        w_qkv, wqkv_ptr, QKV_N);
    pack_w_fp16_kernel<<<((O_DIM / 2) * HIDDEN) / 256, 256>>>(
        w_o, wo_ptr, HIDDEN);

    // 1) QKV projection with fused mRoPE -> fp16 Q/K/V buffers
    gemm_fp16_qkv<<<dim3(QKV_N / 128, T_SEQ / GEMM_BM), 256, GEMM_SMEM_BYTES>>>(
        hid_ptr, wqkv_ptr, positions, T_SEQ, QKV_N, HIDDEN);

    // 2) V key-pair transpose (fp16 -> fp16)
    pack_v_kernel<<<(N_KV * T_SEQ * 64 / 2) / 256, 256>>>();

    // 3) Causal flash attention (full fp16 MMA) -> fp16 output
    attn_tc_kernel<<<dim3(T_SEQ / 128, N_HEADS), 256, ATTN_SMEM_BYTES>>>();

    // 4) Output projection (fp16 MMA) -> fp32 out
    gemm_fp16<<<dim3(O_DIM / 128, T_SEQ / GEMM_BM), 256, GEMM_SMEM_BYTES>>>(
        attn_ptr, wo_ptr, out, T_SEQ, O_DIM, HIDDEN);
}